// round 1
// baseline (speedup 1.0000x reference)
#include <cuda_runtime.h>
#include <cuda_bf16.h>
#include <cstdint>

// Problem constants
#define BATCH   2
#define SEQ     2048
#define DMODEL  1024
#define NHEADS  16
#define DHEAD   64
#define MT      (BATCH * SEQ)        // 4096 rows total

// Scratch buffers (device globals: no cudaMalloc allowed)
__device__ float g_Q[MT * DMODEL];
__device__ float g_K[MT * DMODEL];
__device__ float g_V[MT * DMODEL];
__device__ float g_O[MT * DMODEL];

// ---------------------------------------------------------------------------
// SGEMM:  C[M,N] = A[M,K] * B[N,K]^T   (both operands K-contiguous, "NT")
// 128x128x16 tiles, 256 threads, 8x8 microtile per thread.
// ---------------------------------------------------------------------------
__global__ void __launch_bounds__(256) sgemm_nt_kernel(
    const float* __restrict__ A,
    const float* __restrict__ B,
    float* __restrict__ C,
    int M, int N, int K)
{
    __shared__ float As[16][128];
    __shared__ float Bs[16][128];

    const int tid = threadIdx.x;
    const int tx  = tid & 15;       // 0..15  -> N microtile
    const int ty  = tid >> 4;       // 0..15  -> M microtile
    const int bm  = blockIdx.y;
    const int bn  = blockIdx.x;

    const float* Ab = A + (size_t)bm * 128 * K;
    const float* Bb = B + (size_t)bn * 128 * K;

    float acc[8][8];
#pragma unroll
    for (int i = 0; i < 8; i++)
#pragma unroll
        for (int j = 0; j < 8; j++) acc[i][j] = 0.0f;

    for (int t = 0; t < K; t += 16) {
        // Stage tiles (transposed into [k][row] layout)
#pragma unroll
        for (int u = 0; u < 2; u++) {
            int fidx = tid + u * 256;            // 0..511
            int row  = fidx >> 2;                // 0..127
            int c4   = (fidx & 3) << 2;          // 0,4,8,12
            float4 va = *(const float4*)(Ab + (size_t)row * K + t + c4);
            As[c4 + 0][row] = va.x; As[c4 + 1][row] = va.y;
            As[c4 + 2][row] = va.z; As[c4 + 3][row] = va.w;
            float4 vb = *(const float4*)(Bb + (size_t)row * K + t + c4);
            Bs[c4 + 0][row] = vb.x; Bs[c4 + 1][row] = vb.y;
            Bs[c4 + 2][row] = vb.z; Bs[c4 + 3][row] = vb.w;
        }
        __syncthreads();

#pragma unroll
        for (int k = 0; k < 16; k++) {
            float a[8], b[8];
            *(float4*)&a[0] = *(const float4*)&As[k][ty * 8];
            *(float4*)&a[4] = *(const float4*)&As[k][ty * 8 + 4];
            *(float4*)&b[0] = *(const float4*)&Bs[k][tx * 8];
            *(float4*)&b[4] = *(const float4*)&Bs[k][tx * 8 + 4];
#pragma unroll
            for (int i = 0; i < 8; i++)
#pragma unroll
                for (int j = 0; j < 8; j++)
                    acc[i][j] = fmaf(a[i], b[j], acc[i][j]);
        }
        __syncthreads();
    }

    float* Cb = C + (size_t)(bm * 128 + ty * 8) * N + bn * 128 + tx * 8;
#pragma unroll
    for (int i = 0; i < 8; i++) {
        *(float4*)(Cb + (size_t)i * N)     = *(float4*)&acc[i][0];
        *(float4*)(Cb + (size_t)i * N + 4) = *(float4*)&acc[i][4];
    }
}

// ---------------------------------------------------------------------------
// Flash attention (causal, online softmax).
// Q,K,V,O layout: [B, T, DMODEL], head h occupies columns [h*64, h*64+64).
// Block: 64 query rows x full head (d=64). Grid: (T/64, B*H).
// 256 threads = 16x16; each thread: 4 rows x 4 cols microtile.
// Dynamic smem: Qs,Ks,Vs,Ps each 64x65 floats (pad for bank conflicts).
// ---------------------------------------------------------------------------
#define FA_SMEM_FLOATS (4 * 64 * 65)
#define FA_SMEM_BYTES  (FA_SMEM_FLOATS * 4)

__device__ __forceinline__ float warp16_max(float v) {
    v = fmaxf(v, __shfl_xor_sync(0xffffffffu, v, 8));
    v = fmaxf(v, __shfl_xor_sync(0xffffffffu, v, 4));
    v = fmaxf(v, __shfl_xor_sync(0xffffffffu, v, 2));
    v = fmaxf(v, __shfl_xor_sync(0xffffffffu, v, 1));
    return v;
}
__device__ __forceinline__ float warp16_sum(float v) {
    v += __shfl_xor_sync(0xffffffffu, v, 8);
    v += __shfl_xor_sync(0xffffffffu, v, 4);
    v += __shfl_xor_sync(0xffffffffu, v, 2);
    v += __shfl_xor_sync(0xffffffffu, v, 1);
    return v;
}

__global__ void __launch_bounds__(256) flash_attn_kernel(
    const float* __restrict__ Q,
    const float* __restrict__ K,
    const float* __restrict__ V,
    float* __restrict__ O)
{
    extern __shared__ float sm[];
    float* Qs = sm;                 // [64][65]
    float* Ks = sm + 64 * 65;       // [64][65]
    float* Vs = sm + 2 * 64 * 65;   // [64][65]
    float* Ps = sm + 3 * 64 * 65;   // [64][65]

    const int tid = threadIdx.x;
    const int tx  = tid & 15;
    const int ty  = tid >> 4;
    const int bq  = blockIdx.x;           // query tile (0..31)
    const int bh  = blockIdx.y;           // b*H + h
    const int b   = bh >> 4;
    const int h   = bh & 15;

    const float scale = 0.125f;           // 1/sqrt(64)

    const float* Qp = Q + ((size_t)(b * SEQ + bq * 64)) * DMODEL + h * DHEAD;

    // Load Q tile (64 rows x 64 cols)
#pragma unroll
    for (int u = 0; u < 4; u++) {
        int fidx = tid + u * 256;        // 0..1023
        int row  = fidx >> 4;            // 0..63
        int c4   = (fidx & 15) << 2;     // 0..60
        float4 v = *(const float4*)(Qp + (size_t)row * DMODEL + c4);
        float* dst = &Qs[row * 65 + c4];
        dst[0] = v.x; dst[1] = v.y; dst[2] = v.z; dst[3] = v.w;
    }

    float m_i[4], l_i[4], acc[4][4];
#pragma unroll
    for (int i = 0; i < 4; i++) {
        m_i[i] = -1e30f; l_i[i] = 0.0f;
#pragma unroll
        for (int j = 0; j < 4; j++) acc[i][j] = 0.0f;
    }

    for (int kb = 0; kb <= bq; kb++) {
        __syncthreads();   // prev-iter consumers done; Qs visible on iter 0

        const float* Kp = K + ((size_t)(b * SEQ + kb * 64)) * DMODEL + h * DHEAD;
        const float* Vp = V + ((size_t)(b * SEQ + kb * 64)) * DMODEL + h * DHEAD;
#pragma unroll
        for (int u = 0; u < 4; u++) {
            int fidx = tid + u * 256;
            int row  = fidx >> 4;
            int c4   = (fidx & 15) << 2;
            float4 kv = *(const float4*)(Kp + (size_t)row * DMODEL + c4);
            float* kd = &Ks[row * 65 + c4];
            kd[0] = kv.x; kd[1] = kv.y; kd[2] = kv.z; kd[3] = kv.w;
            float4 vv = *(const float4*)(Vp + (size_t)row * DMODEL + c4);
            float* vd = &Vs[row * 65 + c4];
            vd[0] = vv.x; vd[1] = vv.y; vd[2] = vv.z; vd[3] = vv.w;
        }
        __syncthreads();

        // S = Q * K^T  (4x4 microtile)
        float s[4][4];
#pragma unroll
        for (int i = 0; i < 4; i++)
#pragma unroll
            for (int j = 0; j < 4; j++) s[i][j] = 0.0f;

#pragma unroll 8
        for (int k = 0; k < 64; k++) {
            float q[4], kk[4];
#pragma unroll
            for (int i = 0; i < 4; i++) q[i]  = Qs[(ty * 4 + i) * 65 + k];
#pragma unroll
            for (int j = 0; j < 4; j++) kk[j] = Ks[(tx * 4 + j) * 65 + k];
#pragma unroll
            for (int i = 0; i < 4; i++)
#pragma unroll
                for (int j = 0; j < 4; j++)
                    s[i][j] = fmaf(q[i], kk[j], s[i][j]);
        }

        // Scale + causal mask (only the diagonal tile needs masking)
        const bool diag = (kb == bq);
#pragma unroll
        for (int i = 0; i < 4; i++) {
            int qrow = ty * 4 + i;
#pragma unroll
            for (int j = 0; j < 4; j++) {
                int kcol = tx * 4 + j;
                s[i][j] *= scale;
                if (diag && kcol > qrow) s[i][j] = -1e30f;
            }
        }

        // Online softmax update
        float p[4][4];
#pragma unroll
        for (int i = 0; i < 4; i++) {
            float rm = fmaxf(fmaxf(s[i][0], s[i][1]), fmaxf(s[i][2], s[i][3]));
            rm = warp16_max(rm);
            float m_new = fmaxf(m_i[i], rm);
            float corr  = __expf(m_i[i] - m_new);
            float rs = 0.0f;
#pragma unroll
            for (int j = 0; j < 4; j++) {
                p[i][j] = __expf(s[i][j] - m_new);
                rs += p[i][j];
            }
            rs = warp16_sum(rs);
            l_i[i] = l_i[i] * corr + rs;
            m_i[i] = m_new;
#pragma unroll
            for (int j = 0; j < 4; j++) acc[i][j] *= corr;
        }

        // Stage P for the PV GEMM
#pragma unroll
        for (int i = 0; i < 4; i++)
#pragma unroll
            for (int j = 0; j < 4; j++)
                Ps[(ty * 4 + i) * 65 + tx * 4 + j] = p[i][j];
        __syncthreads();

        // acc += P * V
#pragma unroll 8
        for (int ss = 0; ss < 64; ss++) {
            float pr[4], vv[4];
#pragma unroll
            for (int i = 0; i < 4; i++) pr[i] = Ps[(ty * 4 + i) * 65 + ss];
#pragma unroll
            for (int j = 0; j < 4; j++) vv[j] = Vs[ss * 65 + tx * 4 + j];
#pragma unroll
            for (int i = 0; i < 4; i++)
#pragma unroll
                for (int j = 0; j < 4; j++)
                    acc[i][j] = fmaf(pr[i], vv[j], acc[i][j]);
        }
    }

    // Epilogue: normalize and write O
    float* Op = O + ((size_t)(b * SEQ + bq * 64)) * DMODEL + h * DHEAD;
#pragma unroll
    for (int i = 0; i < 4; i++) {
        float inv = 1.0f / fmaxf(l_i[i], 1e-12f);
        float4 v;
        v.x = acc[i][0] * inv; v.y = acc[i][1] * inv;
        v.z = acc[i][2] * inv; v.w = acc[i][3] * inv;
        *(float4*)(Op + (size_t)(ty * 4 + i) * DMODEL + tx * 4) = v;
    }
}

// ---------------------------------------------------------------------------
// Launch
// ---------------------------------------------------------------------------
extern "C" void kernel_launch(void* const* d_in, const int* in_sizes, int n_in,
                              void* d_out, int out_size)
{
    const float* x  = (const float*)d_in[0];
    const float* Wq = (const float*)d_in[1];
    const float* Wk = (const float*)d_in[2];
    const float* Wv = (const float*)d_in[3];
    const float* Wo = (const float*)d_in[4];
    float* out = (float*)d_out;

    float *Qb, *Kb, *Vb, *Ob;
    cudaGetSymbolAddress((void**)&Qb, g_Q);
    cudaGetSymbolAddress((void**)&Kb, g_K);
    cudaGetSymbolAddress((void**)&Vb, g_V);
    cudaGetSymbolAddress((void**)&Ob, g_O);

    dim3 gemmGrid(DMODEL / 128, MT / 128);   // (8, 32)

    sgemm_nt_kernel<<<gemmGrid, 256>>>(x, Wq, Qb, MT, DMODEL, DMODEL);
    sgemm_nt_kernel<<<gemmGrid, 256>>>(x, Wk, Kb, MT, DMODEL, DMODEL);
    sgemm_nt_kernel<<<gemmGrid, 256>>>(x, Wv, Vb, MT, DMODEL, DMODEL);

    cudaFuncSetAttribute(flash_attn_kernel,
                         cudaFuncAttributeMaxDynamicSharedMemorySize,
                         FA_SMEM_BYTES);
    dim3 faGrid(SEQ / 64, BATCH * NHEADS);   // (32, 32)
    flash_attn_kernel<<<faGrid, 256, FA_SMEM_BYTES>>>(Qb, Kb, Vb, Ob);

    sgemm_nt_kernel<<<gemmGrid, 256>>>(Ob, Wo, out, MT, DMODEL, DMODEL);
}

// round 3
// speedup vs baseline: 1.3862x; 1.3862x over previous
#include <cuda_runtime.h>
#include <cuda_bf16.h>
#include <cstdint>

// Problem constants
#define BATCH   2
#define SEQ     2048
#define DMODEL  1024
#define NHEADS  16
#define DHEAD   64
#define MT      (BATCH * SEQ)        // 4096 rows

// ---------------------------------------------------------------------------
// Scratch (device globals: no cudaMalloc allowed)
// ---------------------------------------------------------------------------
__device__ float g_Q[MT * DMODEL];
__device__ float g_K[MT * DMODEL];
__device__ float g_V[MT * DMODEL];
__device__ float g_O[MT * DMODEL];

__device__ __nv_bfloat16 g_xhi[MT * DMODEL];
__device__ __nv_bfloat16 g_xlo[MT * DMODEL];
__device__ __nv_bfloat16 g_ohi[MT * DMODEL];
__device__ __nv_bfloat16 g_olo[MT * DMODEL];
__device__ __nv_bfloat16 g_whi[4][DMODEL * DMODEL];
__device__ __nv_bfloat16 g_wlo[4][DMODEL * DMODEL];

// ---------------------------------------------------------------------------
// Helpers (base ISA only — no tcgen05: harness PTX target is compute_103)
// ---------------------------------------------------------------------------
__device__ __forceinline__ uint32_t smem_u32(const void* p) {
    uint32_t a;
    asm("{ .reg .u64 t; cvta.to.shared.u64 t, %1; cvt.u32.u64 %0, t; }"
        : "=r"(a) : "l"(p));
    return a;
}

__device__ __forceinline__ uint32_t sw128(uint32_t off) {
    return off ^ ((off >> 3) & 0x70);
}

__device__ __forceinline__ void ldsm4(uint32_t* r, uint32_t addr) {
    asm volatile("ldmatrix.sync.aligned.m8n8.x4.shared.b16 {%0,%1,%2,%3}, [%4];"
        : "=r"(r[0]), "=r"(r[1]), "=r"(r[2]), "=r"(r[3]) : "r"(addr));
}

__device__ __forceinline__ void mma16816(float* c, const uint32_t* a,
                                         uint32_t b0, uint32_t b1) {
    asm volatile(
        "mma.sync.aligned.m16n8k16.row.col.f32.bf16.bf16.f32 "
        "{%0,%1,%2,%3}, {%4,%5,%6,%7}, {%8,%9}, {%0,%1,%2,%3};"
        : "+f"(c[0]), "+f"(c[1]), "+f"(c[2]), "+f"(c[3])
        : "r"(a[0]), "r"(a[1]), "r"(a[2]), "r"(a[3]), "r"(b0), "r"(b1));
}

// ---------------------------------------------------------------------------
// fp32 -> (bf16 hi, bf16 lo) split conversion
// ---------------------------------------------------------------------------
__global__ void __launch_bounds__(256) split_bf16_kernel(
    const float4* __restrict__ in,
    __nv_bfloat162* __restrict__ hi,
    __nv_bfloat162* __restrict__ lo,
    int n4)
{
    int i = blockIdx.x * blockDim.x + threadIdx.x;
    if (i >= n4) return;
    float4 v = in[i];
    __nv_bfloat16 h0 = __float2bfloat16(v.x);
    __nv_bfloat16 h1 = __float2bfloat16(v.y);
    __nv_bfloat16 h2 = __float2bfloat16(v.z);
    __nv_bfloat16 h3 = __float2bfloat16(v.w);
    hi[2 * i]     = __halves2bfloat162(h0, h1);
    hi[2 * i + 1] = __halves2bfloat162(h2, h3);
    lo[2 * i]     = __halves2bfloat162(__float2bfloat16(v.x - __bfloat162float(h0)),
                                       __float2bfloat16(v.y - __bfloat162float(h1)));
    lo[2 * i + 1] = __halves2bfloat162(__float2bfloat16(v.z - __bfloat162float(h2)),
                                       __float2bfloat16(v.w - __bfloat162float(h3)));
}

// ---------------------------------------------------------------------------
// Split-bf16 GEMM via mma.sync (HMMA):  C[M,N] = A[M,K] * B[N,K]^T
// C = Ahi*Bhi + Ahi*Blo + Alo*Bhi (fp32-equivalent to ~1e-5)
// CTA: 128x128 tile, 256 threads = 8 warps (4 M x 2 N), warp tile 32x64.
// K staged in 64-wide chunks: Ahi/Alo/Bhi/Blo each [128][64] bf16, SW128
// swizzled rows of 128B. blockIdx.z selects (B, C) pair for fused QKV.
// ---------------------------------------------------------------------------
#define TILE_BYTES 16384                  // 128*64*2
#define SA_HI 0
#define SA_LO (SA_HI + TILE_BYTES)
#define SB_HI (SA_LO + TILE_BYTES)
#define SB_LO (SB_HI + TILE_BYTES)
#define GSM_TOTAL (4 * TILE_BYTES)        // 64 KB

__global__ void __launch_bounds__(256) gemm_mma_kernel(
    const __nv_bfloat16* __restrict__ Ahi, const __nv_bfloat16* __restrict__ Alo,
    const __nv_bfloat16* __restrict__ B0h, const __nv_bfloat16* __restrict__ B0l, float* C0,
    const __nv_bfloat16* __restrict__ B1h, const __nv_bfloat16* __restrict__ B1l, float* C1,
    const __nv_bfloat16* __restrict__ B2h, const __nv_bfloat16* __restrict__ B2l, float* C2)
{
    extern __shared__ char smem[];
    const uint32_t sbase = smem_u32(smem);

    const int tid  = threadIdx.x;
    const int wid  = tid >> 5;
    const int lane = tid & 31;
    const int warp_m = wid & 3;       // 0..3
    const int warp_n = wid >> 2;      // 0..1
    const int bn = blockIdx.x;
    const int bm = blockIdx.y;
    const int z  = blockIdx.z;

    const __nv_bfloat16* Bh = (z == 0) ? B0h : (z == 1) ? B1h : B2h;
    const __nv_bfloat16* Bl = (z == 0) ? B0l : (z == 1) ? B1l : B2l;
    float* C = (z == 0) ? C0 : (z == 1) ? C1 : C2;

    float acc[2][8][4];
#pragma unroll
    for (int i = 0; i < 2; i++)
#pragma unroll
        for (int j = 0; j < 8; j++)
#pragma unroll
            for (int k = 0; k < 4; k++) acc[i][j][k] = 0.0f;

    // Staging mapping: thread -> (row, 64B half); 4 x 16B stores per tile
    const int lrow  = tid >> 1;              // 0..127
    const int lhalf = (tid & 1) * 64;        // byte offset in 128B row

    const char* gAh = (const char*)(Ahi + (size_t)(bm * 128 + lrow) * DMODEL) + lhalf;
    const char* gAl = (const char*)(Alo + (size_t)(bm * 128 + lrow) * DMODEL) + lhalf;
    const char* gBh = (const char*)(Bh  + (size_t)(bn * 128 + lrow) * DMODEL) + lhalf;
    const char* gBl = (const char*)(Bl  + (size_t)(bn * 128 + lrow) * DMODEL) + lhalf;

    // ldmatrix per-thread address components
    const int a_row16 = lane & 15;                         // row within 16-row tile
    const int a_koff  = (lane >> 4) * 16;                  // 0 or 16 bytes (k half)
    const int b_row16 = (lane & 7) | ((lane & 16) >> 1);   // row within 16-n tile
    const int b_koff  = ((lane >> 3) & 1) * 16;            // 0 or 16 bytes

    for (int t = 0; t < DMODEL / 64; t++) {
        // ---- stage chunk ----
        const int gofs = t * 128;   // 64 bf16 = 128 bytes per k-chunk
#pragma unroll
        for (int i = 0; i < 4; i++) {
            uint32_t so = sw128((uint32_t)(lrow * 128 + lhalf + i * 16));
            *(uint4*)(smem + SA_HI + so) = *(const uint4*)(gAh + gofs + i * 16);
            *(uint4*)(smem + SA_LO + so) = *(const uint4*)(gAl + gofs + i * 16);
            *(uint4*)(smem + SB_HI + so) = *(const uint4*)(gBh + gofs + i * 16);
            *(uint4*)(smem + SB_LO + so) = *(const uint4*)(gBl + gofs + i * 16);
        }
        __syncthreads();

        // ---- compute: 4 k16 steps ----
#pragma unroll
        for (int k16 = 0; k16 < 4; k16++) {
            const int kb = k16 * 32;
            uint32_t ah[2][4], al[2][4];
#pragma unroll
            for (int mt = 0; mt < 2; mt++) {
                int r = warp_m * 32 + mt * 16 + a_row16;
                uint32_t off = sw128((uint32_t)(r * 128 + kb + a_koff));
                ldsm4(ah[mt], sbase + SA_HI + off);
                ldsm4(al[mt], sbase + SA_LO + off);
            }
#pragma unroll
            for (int np = 0; np < 4; np++) {     // pairs of n8 tiles
                int nr = warp_n * 64 + np * 16 + b_row16;
                uint32_t off = sw128((uint32_t)(nr * 128 + kb + b_koff));
                uint32_t bh[4], bl[4];
                ldsm4(bh, sbase + SB_HI + off);
                ldsm4(bl, sbase + SB_LO + off);
#pragma unroll
                for (int mt = 0; mt < 2; mt++) {
                    mma16816(acc[mt][2 * np],     ah[mt], bh[0], bh[1]);
                    mma16816(acc[mt][2 * np],     ah[mt], bl[0], bl[1]);
                    mma16816(acc[mt][2 * np],     al[mt], bh[0], bh[1]);
                    mma16816(acc[mt][2 * np + 1], ah[mt], bh[2], bh[3]);
                    mma16816(acc[mt][2 * np + 1], ah[mt], bl[2], bl[3]);
                    mma16816(acc[mt][2 * np + 1], al[mt], bh[2], bh[3]);
                }
            }
        }
        __syncthreads();
    }

    // ---- epilogue ----
    const int grp = lane >> 2;       // 0..7
    const int tig = lane & 3;        // 0..3
#pragma unroll
    for (int mt = 0; mt < 2; mt++) {
        int row = bm * 128 + warp_m * 32 + mt * 16 + grp;
#pragma unroll
        for (int nt = 0; nt < 8; nt++) {
            int col = bn * 128 + warp_n * 64 + nt * 8 + tig * 2;
            float2 v0 = make_float2(acc[mt][nt][0], acc[mt][nt][1]);
            float2 v1 = make_float2(acc[mt][nt][2], acc[mt][nt][3]);
            *(float2*)(C + (size_t)row * DMODEL + col)       = v0;
            *(float2*)(C + (size_t)(row + 8) * DMODEL + col) = v1;
        }
    }
}

// ---------------------------------------------------------------------------
// Flash attention (causal, online softmax) — fp32, unchanged from round 1
// ---------------------------------------------------------------------------
#define FA_SMEM_FLOATS (4 * 64 * 65)
#define FA_SMEM_BYTES  (FA_SMEM_FLOATS * 4)

__device__ __forceinline__ float warp16_max(float v) {
    v = fmaxf(v, __shfl_xor_sync(0xffffffffu, v, 8));
    v = fmaxf(v, __shfl_xor_sync(0xffffffffu, v, 4));
    v = fmaxf(v, __shfl_xor_sync(0xffffffffu, v, 2));
    v = fmaxf(v, __shfl_xor_sync(0xffffffffu, v, 1));
    return v;
}
__device__ __forceinline__ float warp16_sum(float v) {
    v += __shfl_xor_sync(0xffffffffu, v, 8);
    v += __shfl_xor_sync(0xffffffffu, v, 4);
    v += __shfl_xor_sync(0xffffffffu, v, 2);
    v += __shfl_xor_sync(0xffffffffu, v, 1);
    return v;
}

__global__ void __launch_bounds__(256) flash_attn_kernel(
    const float* __restrict__ Q,
    const float* __restrict__ K,
    const float* __restrict__ V,
    float* __restrict__ O)
{
    extern __shared__ float sm[];
    float* Qs = sm;
    float* Ks = sm + 64 * 65;
    float* Vs = sm + 2 * 64 * 65;
    float* Ps = sm + 3 * 64 * 65;

    const int tid = threadIdx.x;
    const int tx  = tid & 15;
    const int ty  = tid >> 4;
    const int bq  = blockIdx.x;
    const int bh  = blockIdx.y;
    const int b   = bh >> 4;
    const int h   = bh & 15;

    const float scale = 0.125f;

    const float* Qp = Q + ((size_t)(b * SEQ + bq * 64)) * DMODEL + h * DHEAD;

#pragma unroll
    for (int u = 0; u < 4; u++) {
        int fidx = tid + u * 256;
        int row  = fidx >> 4;
        int c4   = (fidx & 15) << 2;
        float4 v = *(const float4*)(Qp + (size_t)row * DMODEL + c4);
        float* dst = &Qs[row * 65 + c4];
        dst[0] = v.x; dst[1] = v.y; dst[2] = v.z; dst[3] = v.w;
    }

    float m_i[4], l_i[4], acc[4][4];
#pragma unroll
    for (int i = 0; i < 4; i++) {
        m_i[i] = -1e30f; l_i[i] = 0.0f;
#pragma unroll
        for (int j = 0; j < 4; j++) acc[i][j] = 0.0f;
    }

    for (int kb = 0; kb <= bq; kb++) {
        __syncthreads();

        const float* Kp = K + ((size_t)(b * SEQ + kb * 64)) * DMODEL + h * DHEAD;
        const float* Vp = V + ((size_t)(b * SEQ + kb * 64)) * DMODEL + h * DHEAD;
#pragma unroll
        for (int u = 0; u < 4; u++) {
            int fidx = tid + u * 256;
            int row  = fidx >> 4;
            int c4   = (fidx & 15) << 2;
            float4 kv = *(const float4*)(Kp + (size_t)row * DMODEL + c4);
            float* kd = &Ks[row * 65 + c4];
            kd[0] = kv.x; kd[1] = kv.y; kd[2] = kv.z; kd[3] = kv.w;
            float4 vv = *(const float4*)(Vp + (size_t)row * DMODEL + c4);
            float* vd = &Vs[row * 65 + c4];
            vd[0] = vv.x; vd[1] = vv.y; vd[2] = vv.z; vd[3] = vv.w;
        }
        __syncthreads();

        float s[4][4];
#pragma unroll
        for (int i = 0; i < 4; i++)
#pragma unroll
            for (int j = 0; j < 4; j++) s[i][j] = 0.0f;

#pragma unroll 8
        for (int k = 0; k < 64; k++) {
            float q[4], kk[4];
#pragma unroll
            for (int i = 0; i < 4; i++) q[i]  = Qs[(ty * 4 + i) * 65 + k];
#pragma unroll
            for (int j = 0; j < 4; j++) kk[j] = Ks[(tx * 4 + j) * 65 + k];
#pragma unroll
            for (int i = 0; i < 4; i++)
#pragma unroll
                for (int j = 0; j < 4; j++)
                    s[i][j] = fmaf(q[i], kk[j], s[i][j]);
        }

        const bool diag = (kb == bq);
#pragma unroll
        for (int i = 0; i < 4; i++) {
            int qrow = ty * 4 + i;
#pragma unroll
            for (int j = 0; j < 4; j++) {
                int kcol = tx * 4 + j;
                s[i][j] *= scale;
                if (diag && kcol > qrow) s[i][j] = -1e30f;
            }
        }

        float p[4][4];
#pragma unroll
        for (int i = 0; i < 4; i++) {
            float rm = fmaxf(fmaxf(s[i][0], s[i][1]), fmaxf(s[i][2], s[i][3]));
            rm = warp16_max(rm);
            float m_new = fmaxf(m_i[i], rm);
            float corr  = __expf(m_i[i] - m_new);
            float rs = 0.0f;
#pragma unroll
            for (int j = 0; j < 4; j++) {
                p[i][j] = __expf(s[i][j] - m_new);
                rs += p[i][j];
            }
            rs = warp16_sum(rs);
            l_i[i] = l_i[i] * corr + rs;
            m_i[i] = m_new;
#pragma unroll
            for (int j = 0; j < 4; j++) acc[i][j] *= corr;
        }

#pragma unroll
        for (int i = 0; i < 4; i++)
#pragma unroll
            for (int j = 0; j < 4; j++)
                Ps[(ty * 4 + i) * 65 + tx * 4 + j] = p[i][j];
        __syncthreads();

#pragma unroll 8
        for (int ss = 0; ss < 64; ss++) {
            float pr[4], vv[4];
#pragma unroll
            for (int i = 0; i < 4; i++) pr[i] = Ps[(ty * 4 + i) * 65 + ss];
#pragma unroll
            for (int j = 0; j < 4; j++) vv[j] = Vs[ss * 65 + tx * 4 + j];
#pragma unroll
            for (int i = 0; i < 4; i++)
#pragma unroll
                for (int j = 0; j < 4; j++)
                    acc[i][j] = fmaf(pr[i], vv[j], acc[i][j]);
        }
    }

    float* Op = O + ((size_t)(b * SEQ + bq * 64)) * DMODEL + h * DHEAD;
#pragma unroll
    for (int i = 0; i < 4; i++) {
        float inv = 1.0f / fmaxf(l_i[i], 1e-12f);
        float4 v;
        v.x = acc[i][0] * inv; v.y = acc[i][1] * inv;
        v.z = acc[i][2] * inv; v.w = acc[i][3] * inv;
        *(float4*)(Op + (size_t)(ty * 4 + i) * DMODEL + tx * 4) = v;
    }
}

// ---------------------------------------------------------------------------
// Launch
// ---------------------------------------------------------------------------
extern "C" void kernel_launch(void* const* d_in, const int* in_sizes, int n_in,
                              void* d_out, int out_size)
{
    const float* x  = (const float*)d_in[0];
    const float* Wq = (const float*)d_in[1];
    const float* Wk = (const float*)d_in[2];
    const float* Wv = (const float*)d_in[3];
    const float* Wo = (const float*)d_in[4];
    float* out = (float*)d_out;

    float *Qb, *Kb, *Vb, *Ob;
    cudaGetSymbolAddress((void**)&Qb, g_Q);
    cudaGetSymbolAddress((void**)&Kb, g_K);
    cudaGetSymbolAddress((void**)&Vb, g_V);
    cudaGetSymbolAddress((void**)&Ob, g_O);

    __nv_bfloat16 *xhi, *xlo, *ohi, *olo, *whi, *wlo;
    cudaGetSymbolAddress((void**)&xhi, g_xhi);
    cudaGetSymbolAddress((void**)&xlo, g_xlo);
    cudaGetSymbolAddress((void**)&ohi, g_ohi);
    cudaGetSymbolAddress((void**)&olo, g_olo);
    cudaGetSymbolAddress((void**)&whi, g_whi);
    cudaGetSymbolAddress((void**)&wlo, g_wlo);

    const int WN  = DMODEL * DMODEL;
    const int xn4 = (MT * DMODEL) / 4;
    const int wn4 = WN / 4;

    split_bf16_kernel<<<(xn4 + 255) / 256, 256>>>(
        (const float4*)x, (__nv_bfloat162*)xhi, (__nv_bfloat162*)xlo, xn4);
    const float* Ws[4] = {Wq, Wk, Wv, Wo};
    for (int i = 0; i < 4; i++) {
        split_bf16_kernel<<<(wn4 + 255) / 256, 256>>>(
            (const float4*)Ws[i],
            (__nv_bfloat162*)(whi + (size_t)i * WN),
            (__nv_bfloat162*)(wlo + (size_t)i * WN), wn4);
    }

    cudaFuncSetAttribute(gemm_mma_kernel,
                         cudaFuncAttributeMaxDynamicSharedMemorySize, GSM_TOTAL);

    dim3 qkvGrid(DMODEL / 128, MT / 128, 3);
    gemm_mma_kernel<<<qkvGrid, 256, GSM_TOTAL>>>(
        xhi, xlo,
        whi + 0 * (size_t)WN, wlo + 0 * (size_t)WN, Qb,
        whi + 1 * (size_t)WN, wlo + 1 * (size_t)WN, Kb,
        whi + 2 * (size_t)WN, wlo + 2 * (size_t)WN, Vb);

    cudaFuncSetAttribute(flash_attn_kernel,
                         cudaFuncAttributeMaxDynamicSharedMemorySize, FA_SMEM_BYTES);
    dim3 faGrid(SEQ / 64, BATCH * NHEADS);
    flash_attn_kernel<<<faGrid, 256, FA_SMEM_BYTES>>>(Qb, Kb, Vb, Ob);

    split_bf16_kernel<<<(xn4 + 255) / 256, 256>>>(
        (const float4*)Ob, (__nv_bfloat162*)ohi, (__nv_bfloat162*)olo, xn4);
    dim3 oGrid(DMODEL / 128, MT / 128, 1);
    gemm_mma_kernel<<<oGrid, 256, GSM_TOTAL>>>(
        ohi, olo,
        whi + 3 * (size_t)WN, wlo + 3 * (size_t)WN, out,
        whi + 3 * (size_t)WN, wlo + 3 * (size_t)WN, out,
        whi + 3 * (size_t)WN, wlo + 3 * (size_t)WN, out);
}

// round 4
// speedup vs baseline: 2.3579x; 1.7010x over previous
#include <cuda_runtime.h>
#include <cuda_bf16.h>
#include <cstdint>

// Problem constants
#define BATCH   2
#define SEQ     2048
#define DMODEL  1024
#define NHEADS  16
#define DHEAD   64
#define MT      (BATCH * SEQ)        // 4096 rows

// ---------------------------------------------------------------------------
// Scratch (device globals: no cudaMalloc allowed)
// ---------------------------------------------------------------------------
__device__ float g_O[MT * DMODEL];

__device__ __nv_bfloat16 g_xhi[MT * DMODEL];
__device__ __nv_bfloat16 g_xlo[MT * DMODEL];
__device__ __nv_bfloat16 g_ohi[MT * DMODEL];
__device__ __nv_bfloat16 g_olo[MT * DMODEL];
__device__ __nv_bfloat16 g_whi[4][DMODEL * DMODEL];
__device__ __nv_bfloat16 g_wlo[4][DMODEL * DMODEL];

__device__ __nv_bfloat16 g_Qhi[MT * DMODEL];
__device__ __nv_bfloat16 g_Qlo[MT * DMODEL];
__device__ __nv_bfloat16 g_Khi[MT * DMODEL];
__device__ __nv_bfloat16 g_Klo[MT * DMODEL];
__device__ __nv_bfloat16 g_Vthi[MT * DMODEL];   // [b][h][d][t]
__device__ __nv_bfloat16 g_Vtlo[MT * DMODEL];

// ---------------------------------------------------------------------------
// Helpers (base ISA only — harness PTX target is compute_103, no tcgen05)
// ---------------------------------------------------------------------------
__device__ __forceinline__ uint32_t smem_u32(const void* p) {
    uint32_t a;
    asm("{ .reg .u64 t; cvta.to.shared.u64 t, %1; cvt.u32.u64 %0, t; }"
        : "=r"(a) : "l"(p));
    return a;
}

__device__ __forceinline__ uint32_t sw128(uint32_t off) {
    return off ^ ((off >> 3) & 0x70);
}

__device__ __forceinline__ void ldsm4(uint32_t* r, uint32_t addr) {
    asm volatile("ldmatrix.sync.aligned.m8n8.x4.shared.b16 {%0,%1,%2,%3}, [%4];"
        : "=r"(r[0]), "=r"(r[1]), "=r"(r[2]), "=r"(r[3]) : "r"(addr));
}

__device__ __forceinline__ void mma16816(float* c, const uint32_t* a,
                                         uint32_t b0, uint32_t b1) {
    asm volatile(
        "mma.sync.aligned.m16n8k16.row.col.f32.bf16.bf16.f32 "
        "{%0,%1,%2,%3}, {%4,%5,%6,%7}, {%8,%9}, {%0,%1,%2,%3};"
        : "+f"(c[0]), "+f"(c[1]), "+f"(c[2]), "+f"(c[3])
        : "r"(a[0]), "r"(a[1]), "r"(a[2]), "r"(a[3]), "r"(b0), "r"(b1));
}

// split two floats into packed bf16 hi/lo pairs
__device__ __forceinline__ void split_pack(float x, float y, uint32_t& hi, uint32_t& lo) {
    __nv_bfloat16 hx = __float2bfloat16(x), hy = __float2bfloat16(y);
    __nv_bfloat16 lx = __float2bfloat16(x - __bfloat162float(hx));
    __nv_bfloat16 ly = __float2bfloat16(y - __bfloat162float(hy));
    __nv_bfloat162 h2 = __halves2bfloat162(hx, hy);
    __nv_bfloat162 l2 = __halves2bfloat162(lx, ly);
    hi = *(uint32_t*)&h2;
    lo = *(uint32_t*)&l2;
}

// ---------------------------------------------------------------------------
// fp32 -> (bf16 hi, bf16 lo) split conversion
// ---------------------------------------------------------------------------
__global__ void __launch_bounds__(256) split_bf16_kernel(
    const float4* __restrict__ in,
    __nv_bfloat162* __restrict__ hi,
    __nv_bfloat162* __restrict__ lo,
    int n4)
{
    int i = blockIdx.x * blockDim.x + threadIdx.x;
    if (i >= n4) return;
    float4 v = in[i];
    uint32_t h0, l0, h1, l1;
    split_pack(v.x, v.y, h0, l0);
    split_pack(v.z, v.w, h1, l1);
    ((uint32_t*)hi)[2 * i]     = h0;
    ((uint32_t*)hi)[2 * i + 1] = h1;
    ((uint32_t*)lo)[2 * i]     = l0;
    ((uint32_t*)lo)[2 * i + 1] = l1;
}

// ---------------------------------------------------------------------------
// Split-bf16 GEMM via mma.sync:  C[M,N] = A[M,K] * B[N,K]^T
// C = Ahi*Bhi + Ahi*Blo + Alo*Bhi
// CTA: 128x128 tile, 256 threads = 8 warps (4 M x 2 N), warp tile 32x64.
// qkv=1: z=0 -> Q split-bf16 out, z=1 -> K split-bf16, z=2 -> V split-bf16
//        TRANSPOSED per head ([b][h][d][t]).
// qkv=0: fp32 out to C.
// ---------------------------------------------------------------------------
#define TILE_BYTES 16384                  // 128*64*2
#define SA_HI 0
#define SA_LO (SA_HI + TILE_BYTES)
#define SB_HI (SA_LO + TILE_BYTES)
#define SB_LO (SB_HI + TILE_BYTES)
#define GSM_TOTAL (4 * TILE_BYTES)        // 64 KB

__global__ void __launch_bounds__(256) gemm_mma_kernel(
    const __nv_bfloat16* __restrict__ Ahi, const __nv_bfloat16* __restrict__ Alo,
    const __nv_bfloat16* __restrict__ B0h, const __nv_bfloat16* __restrict__ B0l,
    const __nv_bfloat16* __restrict__ B1h, const __nv_bfloat16* __restrict__ B1l,
    const __nv_bfloat16* __restrict__ B2h, const __nv_bfloat16* __restrict__ B2l,
    float* __restrict__ C,
    __nv_bfloat16* __restrict__ Qh, __nv_bfloat16* __restrict__ Ql,
    __nv_bfloat16* __restrict__ Kh, __nv_bfloat16* __restrict__ Kl,
    __nv_bfloat16* __restrict__ Vth, __nv_bfloat16* __restrict__ Vtl,
    int qkv)
{
    extern __shared__ char smem[];
    const uint32_t sbase = smem_u32(smem);

    const int tid  = threadIdx.x;
    const int wid  = tid >> 5;
    const int lane = tid & 31;
    const int warp_m = wid & 3;
    const int warp_n = wid >> 2;
    const int bn = blockIdx.x;
    const int bm = blockIdx.y;
    const int z  = blockIdx.z;

    const __nv_bfloat16* Bh = (z == 0) ? B0h : (z == 1) ? B1h : B2h;
    const __nv_bfloat16* Bl = (z == 0) ? B0l : (z == 1) ? B1l : B2l;

    float acc[2][8][4];
#pragma unroll
    for (int i = 0; i < 2; i++)
#pragma unroll
        for (int j = 0; j < 8; j++)
#pragma unroll
            for (int k = 0; k < 4; k++) acc[i][j][k] = 0.0f;

    const int lrow  = tid >> 1;
    const int lhalf = (tid & 1) * 64;

    const char* gAh = (const char*)(Ahi + (size_t)(bm * 128 + lrow) * DMODEL) + lhalf;
    const char* gAl = (const char*)(Alo + (size_t)(bm * 128 + lrow) * DMODEL) + lhalf;
    const char* gBh = (const char*)(Bh  + (size_t)(bn * 128 + lrow) * DMODEL) + lhalf;
    const char* gBl = (const char*)(Bl  + (size_t)(bn * 128 + lrow) * DMODEL) + lhalf;

    const int a_row16 = lane & 15;
    const int a_koff  = (lane >> 4) * 16;
    const int b_row16 = (lane & 7) | ((lane & 16) >> 1);
    const int b_koff  = ((lane >> 3) & 1) * 16;

    for (int t = 0; t < DMODEL / 64; t++) {
        const int gofs = t * 128;
#pragma unroll
        for (int i = 0; i < 4; i++) {
            uint32_t so = sw128((uint32_t)(lrow * 128 + lhalf + i * 16));
            *(uint4*)(smem + SA_HI + so) = *(const uint4*)(gAh + gofs + i * 16);
            *(uint4*)(smem + SA_LO + so) = *(const uint4*)(gAl + gofs + i * 16);
            *(uint4*)(smem + SB_HI + so) = *(const uint4*)(gBh + gofs + i * 16);
            *(uint4*)(smem + SB_LO + so) = *(const uint4*)(gBl + gofs + i * 16);
        }
        __syncthreads();

#pragma unroll
        for (int k16 = 0; k16 < 4; k16++) {
            const int kb = k16 * 32;
            uint32_t ah[2][4], al[2][4];
#pragma unroll
            for (int mt = 0; mt < 2; mt++) {
                int r = warp_m * 32 + mt * 16 + a_row16;
                uint32_t off = sw128((uint32_t)(r * 128 + kb + a_koff));
                ldsm4(ah[mt], sbase + SA_HI + off);
                ldsm4(al[mt], sbase + SA_LO + off);
            }
#pragma unroll
            for (int np = 0; np < 4; np++) {
                int nr = warp_n * 64 + np * 16 + b_row16;
                uint32_t off = sw128((uint32_t)(nr * 128 + kb + b_koff));
                uint32_t bhf[4], blf[4];
                ldsm4(bhf, sbase + SB_HI + off);
                ldsm4(blf, sbase + SB_LO + off);
#pragma unroll
                for (int mt = 0; mt < 2; mt++) {
                    mma16816(acc[mt][2 * np],     ah[mt], bhf[0], bhf[1]);
                    mma16816(acc[mt][2 * np],     ah[mt], blf[0], blf[1]);
                    mma16816(acc[mt][2 * np],     al[mt], bhf[0], bhf[1]);
                    mma16816(acc[mt][2 * np + 1], ah[mt], bhf[2], bhf[3]);
                    mma16816(acc[mt][2 * np + 1], ah[mt], blf[2], blf[3]);
                    mma16816(acc[mt][2 * np + 1], al[mt], bhf[2], bhf[3]);
                }
            }
        }
        __syncthreads();
    }

    // ---- epilogue ----
    const int mode = qkv ? ((z == 2) ? 2 : 1) : 0;
    const int grp = lane >> 2;
    const int tig = lane & 3;
    __nv_bfloat16* Hp = (z == 0) ? Qh : Kh;
    __nv_bfloat16* Lp = (z == 0) ? Ql : Kl;

#pragma unroll
    for (int mt = 0; mt < 2; mt++) {
        int row = bm * 128 + warp_m * 32 + mt * 16 + grp;
#pragma unroll
        for (int nt = 0; nt < 8; nt++) {
            int col = bn * 128 + warp_n * 64 + nt * 8 + tig * 2;
            float v00 = acc[mt][nt][0], v01 = acc[mt][nt][1];
            float v10 = acc[mt][nt][2], v11 = acc[mt][nt][3];
            if (mode == 0) {
                *(float2*)(C + (size_t)row * DMODEL + col)       = make_float2(v00, v01);
                *(float2*)(C + (size_t)(row + 8) * DMODEL + col) = make_float2(v10, v11);
            } else if (mode == 1) {
                uint32_t h0, l0, h1, l1;
                split_pack(v00, v01, h0, l0);
                split_pack(v10, v11, h1, l1);
                *(uint32_t*)(Hp + (size_t)row * DMODEL + col)       = h0;
                *(uint32_t*)(Hp + (size_t)(row + 8) * DMODEL + col) = h1;
                *(uint32_t*)(Lp + (size_t)row * DMODEL + col)       = l0;
                *(uint32_t*)(Lp + (size_t)(row + 8) * DMODEL + col) = l1;
            } else {
                // V: write transposed per head: idx = (b*DMODEL + col)*SEQ + t
                int bb = row >> 11;
                int tt = row & (SEQ - 1);
                size_t base0 = (size_t)(bb * DMODEL + col) * SEQ;
                size_t base1 = (size_t)(bb * DMODEL + col + 1) * SEQ;
                __nv_bfloat16 h00 = __float2bfloat16(v00);
                __nv_bfloat16 h01 = __float2bfloat16(v01);
                __nv_bfloat16 h10 = __float2bfloat16(v10);
                __nv_bfloat16 h11 = __float2bfloat16(v11);
                Vth[base0 + tt]     = h00;
                Vth[base1 + tt]     = h01;
                Vth[base0 + tt + 8] = h10;
                Vth[base1 + tt + 8] = h11;
                Vtl[base0 + tt]     = __float2bfloat16(v00 - __bfloat162float(h00));
                Vtl[base1 + tt]     = __float2bfloat16(v01 - __bfloat162float(h01));
                Vtl[base0 + tt + 8] = __float2bfloat16(v10 - __bfloat162float(h10));
                Vtl[base1 + tt + 8] = __float2bfloat16(v11 - __bfloat162float(h11));
            }
        }
    }
}

// ---------------------------------------------------------------------------
// Flash attention via mma.sync (causal, online softmax, split-bf16).
// CTA: 64 q-rows x d=64, kv tiles of 64. 128 threads = 4 warps (m16 each).
// smem: K hi/lo [64][64], Vt hi/lo [64][64] (d-major), Q hi/lo [64][64].
// ---------------------------------------------------------------------------
#define FA_KHI 0
#define FA_KLO 8192
#define FA_VHI 16384
#define FA_VLO 24576
#define FA_QHI 32768
#define FA_QLO 40960
#define FA_TOTAL 49152

__global__ void __launch_bounds__(128) fa_mma_kernel(
    const __nv_bfloat16* __restrict__ Qhi, const __nv_bfloat16* __restrict__ Qlo,
    const __nv_bfloat16* __restrict__ Khi, const __nv_bfloat16* __restrict__ Klo,
    const __nv_bfloat16* __restrict__ Vthi, const __nv_bfloat16* __restrict__ Vtlo,
    float* __restrict__ O)
{
    extern __shared__ char smem[];
    const uint32_t sbase = smem_u32(smem);
    const int tid  = threadIdx.x;
    const int wid  = tid >> 5;
    const int lane = tid & 31;
    const int bq = blockIdx.x;
    const int bh = blockIdx.y;
    const int b  = bh >> 4;
    const int h  = bh & 15;

    const int grp = lane >> 2;
    const int tig = lane & 3;
    const int a_row16 = lane & 15;
    const int a_koff  = (lane >> 4) * 16;
    const int b_row16 = (lane & 7) | ((lane & 16) >> 1);
    const int b_koff  = ((lane >> 3) & 1) * 16;

    // ---- stage Q (hi+lo), once ----
    {
        const char* gqh = (const char*)Qhi + ((size_t)(b * SEQ + bq * 64) * DMODEL + h * 64) * 2;
        const char* gql = (const char*)Qlo + ((size_t)(b * SEQ + bq * 64) * DMODEL + h * 64) * 2;
#pragma unroll
        for (int u = 0; u < 4; u++) {
            int f = u * 128 + tid;
            int row = f >> 3;
            int c16 = (f & 7) * 16;
            uint32_t so = sw128((uint32_t)(row * 128 + c16));
            *(uint4*)(smem + FA_QHI + so) = *(const uint4*)(gqh + (size_t)row * DMODEL * 2 + c16);
            *(uint4*)(smem + FA_QLO + so) = *(const uint4*)(gql + (size_t)row * DMODEL * 2 + c16);
        }
    }

    float oacc[8][4];
#pragma unroll
    for (int i = 0; i < 8; i++)
#pragma unroll
        for (int j = 0; j < 4; j++) oacc[i][j] = 0.0f;
    float m0 = -1e30f, m1 = -1e30f, l0 = 0.0f, l1 = 0.0f;

    const char* gkh = (const char*)Khi + ((size_t)(b * SEQ) * DMODEL + h * 64) * 2;
    const char* gkl = (const char*)Klo + ((size_t)(b * SEQ) * DMODEL + h * 64) * 2;
    const char* gvh = (const char*)Vthi + ((size_t)bh * DHEAD * SEQ) * 2;
    const char* gvl = (const char*)Vtlo + ((size_t)bh * DHEAD * SEQ) * 2;

    const int qrow0 = wid * 16 + grp;   // local q row of this thread's r0

    for (int kb = 0; kb <= bq; kb++) {
        __syncthreads();
        // ---- stage K (rows=kv token) and Vt (rows=d) ----
#pragma unroll
        for (int u = 0; u < 4; u++) {
            int f = u * 128 + tid;
            int row = f >> 3;
            int c16 = (f & 7) * 16;
            uint32_t so = sw128((uint32_t)(row * 128 + c16));
            size_t ko = ((size_t)(kb * 64 + row) * DMODEL) * 2 + c16;
            *(uint4*)(smem + FA_KHI + so) = *(const uint4*)(gkh + ko);
            *(uint4*)(smem + FA_KLO + so) = *(const uint4*)(gkl + ko);
            size_t vo = ((size_t)row * SEQ + kb * 64) * 2 + c16;
            *(uint4*)(smem + FA_VHI + so) = *(const uint4*)(gvh + vo);
            *(uint4*)(smem + FA_VLO + so) = *(const uint4*)(gvl + vo);
        }
        __syncthreads();

        // ---- S = Q K^T (3-term split) ----
        float sacc[8][4];
#pragma unroll
        for (int i = 0; i < 8; i++)
#pragma unroll
            for (int j = 0; j < 4; j++) sacc[i][j] = 0.0f;

#pragma unroll
        for (int k16 = 0; k16 < 4; k16++) {
            uint32_t ah[4], al[4];
            uint32_t aoff = sw128((uint32_t)((wid * 16 + a_row16) * 128 + k16 * 32 + a_koff));
            ldsm4(ah, sbase + FA_QHI + aoff);
            ldsm4(al, sbase + FA_QLO + aoff);
#pragma unroll
            for (int np = 0; np < 4; np++) {
                uint32_t boff = sw128((uint32_t)((np * 16 + b_row16) * 128 + k16 * 32 + b_koff));
                uint32_t bhf[4], blf[4];
                ldsm4(bhf, sbase + FA_KHI + boff);
                ldsm4(blf, sbase + FA_KLO + boff);
                mma16816(sacc[2 * np],     ah, bhf[0], bhf[1]);
                mma16816(sacc[2 * np],     ah, blf[0], blf[1]);
                mma16816(sacc[2 * np],     al, bhf[0], bhf[1]);
                mma16816(sacc[2 * np + 1], ah, bhf[2], bhf[3]);
                mma16816(sacc[2 * np + 1], ah, blf[2], blf[3]);
                mma16816(sacc[2 * np + 1], al, bhf[2], bhf[3]);
            }
        }

        // ---- scale + causal mask ----
        const float scale = 0.125f;
        const bool diag = (kb == bq);
#pragma unroll
        for (int nt = 0; nt < 8; nt++) {
            int c0 = nt * 8 + tig * 2;
            sacc[nt][0] *= scale; sacc[nt][1] *= scale;
            sacc[nt][2] *= scale; sacc[nt][3] *= scale;
            if (diag) {
                if (c0     > qrow0)     sacc[nt][0] = -1e30f;
                if (c0 + 1 > qrow0)     sacc[nt][1] = -1e30f;
                if (c0     > qrow0 + 8) sacc[nt][2] = -1e30f;
                if (c0 + 1 > qrow0 + 8) sacc[nt][3] = -1e30f;
            }
        }

        // ---- online softmax ----
        float rm0 = -1e30f, rm1 = -1e30f;
#pragma unroll
        for (int nt = 0; nt < 8; nt++) {
            rm0 = fmaxf(rm0, fmaxf(sacc[nt][0], sacc[nt][1]));
            rm1 = fmaxf(rm1, fmaxf(sacc[nt][2], sacc[nt][3]));
        }
        rm0 = fmaxf(rm0, __shfl_xor_sync(0xffffffffu, rm0, 1));
        rm0 = fmaxf(rm0, __shfl_xor_sync(0xffffffffu, rm0, 2));
        rm1 = fmaxf(rm1, __shfl_xor_sync(0xffffffffu, rm1, 1));
        rm1 = fmaxf(rm1, __shfl_xor_sync(0xffffffffu, rm1, 2));

        float mn0 = fmaxf(m0, rm0), mn1 = fmaxf(m1, rm1);
        float corr0 = __expf(m0 - mn0), corr1 = __expf(m1 - mn1);
        float rs0 = 0.0f, rs1 = 0.0f;
#pragma unroll
        for (int nt = 0; nt < 8; nt++) {
            sacc[nt][0] = __expf(sacc[nt][0] - mn0);
            sacc[nt][1] = __expf(sacc[nt][1] - mn0);
            sacc[nt][2] = __expf(sacc[nt][2] - mn1);
            sacc[nt][3] = __expf(sacc[nt][3] - mn1);
            rs0 += sacc[nt][0] + sacc[nt][1];
            rs1 += sacc[nt][2] + sacc[nt][3];
        }
        rs0 += __shfl_xor_sync(0xffffffffu, rs0, 1);
        rs0 += __shfl_xor_sync(0xffffffffu, rs0, 2);
        rs1 += __shfl_xor_sync(0xffffffffu, rs1, 1);
        rs1 += __shfl_xor_sync(0xffffffffu, rs1, 2);

        l0 = l0 * corr0 + rs0;
        l1 = l1 * corr1 + rs1;
        m0 = mn0; m1 = mn1;
#pragma unroll
        for (int nt = 0; nt < 8; nt++) {
            oacc[nt][0] *= corr0; oacc[nt][1] *= corr0;
            oacc[nt][2] *= corr1; oacc[nt][3] *= corr1;
        }

        // ---- O += P V (3-term split; P from registers) ----
#pragma unroll
        for (int j = 0; j < 4; j++) {
            uint32_t ph[4], pl[4];
            split_pack(sacc[2 * j][0],     sacc[2 * j][1],     ph[0], pl[0]);
            split_pack(sacc[2 * j][2],     sacc[2 * j][3],     ph[1], pl[1]);
            split_pack(sacc[2 * j + 1][0], sacc[2 * j + 1][1], ph[2], pl[2]);
            split_pack(sacc[2 * j + 1][2], sacc[2 * j + 1][3], ph[3], pl[3]);
#pragma unroll
            for (int nd = 0; nd < 4; nd++) {
                uint32_t boff = sw128((uint32_t)((nd * 16 + b_row16) * 128 + j * 32 + b_koff));
                uint32_t vh[4], vl[4];
                ldsm4(vh, sbase + FA_VHI + boff);
                ldsm4(vl, sbase + FA_VLO + boff);
                mma16816(oacc[2 * nd],     ph, vh[0], vh[1]);
                mma16816(oacc[2 * nd],     ph, vl[0], vl[1]);
                mma16816(oacc[2 * nd],     pl, vh[0], vh[1]);
                mma16816(oacc[2 * nd + 1], ph, vh[2], vh[3]);
                mma16816(oacc[2 * nd + 1], ph, vl[2], vl[3]);
                mma16816(oacc[2 * nd + 1], pl, vh[2], vh[3]);
            }
        }
    }

    // ---- epilogue ----
    float inv0 = 1.0f / l0;
    float inv1 = 1.0f / l1;
    float* Ob = O + ((size_t)(b * SEQ + bq * 64 + wid * 16 + grp)) * DMODEL + h * 64;
#pragma unroll
    for (int nt = 0; nt < 8; nt++) {
        int col = nt * 8 + tig * 2;
        *(float2*)(Ob + col) = make_float2(oacc[nt][0] * inv0, oacc[nt][1] * inv0);
        *(float2*)(Ob + (size_t)8 * DMODEL + col) = make_float2(oacc[nt][2] * inv1, oacc[nt][3] * inv1);
    }
}

// ---------------------------------------------------------------------------
// Launch
// ---------------------------------------------------------------------------
extern "C" void kernel_launch(void* const* d_in, const int* in_sizes, int n_in,
                              void* d_out, int out_size)
{
    const float* x  = (const float*)d_in[0];
    const float* Wq = (const float*)d_in[1];
    const float* Wk = (const float*)d_in[2];
    const float* Wv = (const float*)d_in[3];
    const float* Wo = (const float*)d_in[4];
    float* out = (float*)d_out;

    float* Ob;
    cudaGetSymbolAddress((void**)&Ob, g_O);

    __nv_bfloat16 *xhi, *xlo, *ohi, *olo, *whi, *wlo;
    __nv_bfloat16 *Qh, *Ql, *Kh, *Kl, *Vth, *Vtl;
    cudaGetSymbolAddress((void**)&xhi, g_xhi);
    cudaGetSymbolAddress((void**)&xlo, g_xlo);
    cudaGetSymbolAddress((void**)&ohi, g_ohi);
    cudaGetSymbolAddress((void**)&olo, g_olo);
    cudaGetSymbolAddress((void**)&whi, g_whi);
    cudaGetSymbolAddress((void**)&wlo, g_wlo);
    cudaGetSymbolAddress((void**)&Qh,  g_Qhi);
    cudaGetSymbolAddress((void**)&Ql,  g_Qlo);
    cudaGetSymbolAddress((void**)&Kh,  g_Khi);
    cudaGetSymbolAddress((void**)&Kl,  g_Klo);
    cudaGetSymbolAddress((void**)&Vth, g_Vthi);
    cudaGetSymbolAddress((void**)&Vtl, g_Vtlo);

    const int WN  = DMODEL * DMODEL;
    const int xn4 = (MT * DMODEL) / 4;
    const int wn4 = WN / 4;

    split_bf16_kernel<<<(xn4 + 255) / 256, 256>>>(
        (const float4*)x, (__nv_bfloat162*)xhi, (__nv_bfloat162*)xlo, xn4);
    const float* Ws[4] = {Wq, Wk, Wv, Wo};
    for (int i = 0; i < 4; i++) {
        split_bf16_kernel<<<(wn4 + 255) / 256, 256>>>(
            (const float4*)Ws[i],
            (__nv_bfloat162*)(whi + (size_t)i * WN),
            (__nv_bfloat162*)(wlo + (size_t)i * WN), wn4);
    }

    cudaFuncSetAttribute(gemm_mma_kernel,
                         cudaFuncAttributeMaxDynamicSharedMemorySize, GSM_TOTAL);
    cudaFuncSetAttribute(fa_mma_kernel,
                         cudaFuncAttributeMaxDynamicSharedMemorySize, FA_TOTAL);

    // QKV projections: z=0 -> Q split, z=1 -> K split, z=2 -> V split transposed
    dim3 qkvGrid(DMODEL / 128, MT / 128, 3);
    gemm_mma_kernel<<<qkvGrid, 256, GSM_TOTAL>>>(
        xhi, xlo,
        whi + 0 * (size_t)WN, wlo + 0 * (size_t)WN,
        whi + 1 * (size_t)WN, wlo + 1 * (size_t)WN,
        whi + 2 * (size_t)WN, wlo + 2 * (size_t)WN,
        nullptr, Qh, Ql, Kh, Kl, Vth, Vtl, 1);

    // Flash attention (tensor-core)
    dim3 faGrid(SEQ / 64, BATCH * NHEADS);
    fa_mma_kernel<<<faGrid, 128, FA_TOTAL>>>(Qh, Ql, Kh, Kl, Vth, Vtl, Ob);

    // O projection
    split_bf16_kernel<<<(xn4 + 255) / 256, 256>>>(
        (const float4*)Ob, (__nv_bfloat162*)ohi, (__nv_bfloat162*)olo, xn4);
    dim3 oGrid(DMODEL / 128, MT / 128, 1);
    gemm_mma_kernel<<<oGrid, 256, GSM_TOTAL>>>(
        ohi, olo,
        whi + 3 * (size_t)WN, wlo + 3 * (size_t)WN,
        whi + 3 * (size_t)WN, wlo + 3 * (size_t)WN,
        whi + 3 * (size_t)WN, wlo + 3 * (size_t)WN,
        out, nullptr, nullptr, nullptr, nullptr, nullptr, nullptr, 0);
}

// round 5
// speedup vs baseline: 2.8478x; 1.2078x over previous
#include <cuda_runtime.h>
#include <cuda_bf16.h>
#include <cstdint>

// Problem constants
#define BATCH   2
#define SEQ     2048
#define DMODEL  1024
#define NHEADS  16
#define DHEAD   64
#define MT      (BATCH * SEQ)        // 4096 rows

// ---------------------------------------------------------------------------
// Scratch (device globals: no cudaMalloc allowed)
// ---------------------------------------------------------------------------
__device__ float g_O[MT * DMODEL];

__device__ __nv_bfloat16 g_xhi[MT * DMODEL];
__device__ __nv_bfloat16 g_xlo[MT * DMODEL];
__device__ __nv_bfloat16 g_ohi[MT * DMODEL];
__device__ __nv_bfloat16 g_olo[MT * DMODEL];
__device__ __nv_bfloat16 g_whi[4][DMODEL * DMODEL];
__device__ __nv_bfloat16 g_wlo[4][DMODEL * DMODEL];

__device__ __nv_bfloat16 g_Qhi[MT * DMODEL];
__device__ __nv_bfloat16 g_Qlo[MT * DMODEL];
__device__ __nv_bfloat16 g_Khi[MT * DMODEL];
__device__ __nv_bfloat16 g_Klo[MT * DMODEL];
__device__ __nv_bfloat16 g_Vthi[MT * DMODEL];   // [b][h][d][t]
__device__ __nv_bfloat16 g_Vtlo[MT * DMODEL];

// ---------------------------------------------------------------------------
// Helpers (base ISA only — harness PTX target is compute_103, no tcgen05)
// ---------------------------------------------------------------------------
__device__ __forceinline__ uint32_t smem_u32(const void* p) {
    uint32_t a;
    asm("{ .reg .u64 t; cvta.to.shared.u64 t, %1; cvt.u32.u64 %0, t; }"
        : "=r"(a) : "l"(p));
    return a;
}

__device__ __forceinline__ uint32_t sw128(uint32_t off) {
    return off ^ ((off >> 3) & 0x70);
}

__device__ __forceinline__ void ldsm4(uint32_t* r, uint32_t addr) {
    asm volatile("ldmatrix.sync.aligned.m8n8.x4.shared.b16 {%0,%1,%2,%3}, [%4];"
        : "=r"(r[0]), "=r"(r[1]), "=r"(r[2]), "=r"(r[3]) : "r"(addr));
}

__device__ __forceinline__ void mma16816(float* c, const uint32_t* a,
                                         uint32_t b0, uint32_t b1) {
    asm volatile(
        "mma.sync.aligned.m16n8k16.row.col.f32.bf16.bf16.f32 "
        "{%0,%1,%2,%3}, {%4,%5,%6,%7}, {%8,%9}, {%0,%1,%2,%3};"
        : "+f"(c[0]), "+f"(c[1]), "+f"(c[2]), "+f"(c[3])
        : "r"(a[0]), "r"(a[1]), "r"(a[2]), "r"(a[3]), "r"(b0), "r"(b1));
}

__device__ __forceinline__ void cp16(uint32_t dst, const void* src) {
    asm volatile("cp.async.cg.shared.global [%0], [%1], 16;"
                 :: "r"(dst), "l"(src));
}
#define CP_COMMIT()  asm volatile("cp.async.commit_group;")
#define CP_WAIT(N)   asm volatile("cp.async.wait_group %0;" :: "n"(N))

// split two floats into packed bf16 hi/lo pairs
__device__ __forceinline__ void split_pack(float x, float y, uint32_t& hi, uint32_t& lo) {
    __nv_bfloat16 hx = __float2bfloat16(x), hy = __float2bfloat16(y);
    __nv_bfloat16 lx = __float2bfloat16(x - __bfloat162float(hx));
    __nv_bfloat16 ly = __float2bfloat16(y - __bfloat162float(hy));
    __nv_bfloat162 h2 = __halves2bfloat162(hx, hy);
    __nv_bfloat162 l2 = __halves2bfloat162(lx, ly);
    hi = *(uint32_t*)&h2;
    lo = *(uint32_t*)&l2;
}

// ---------------------------------------------------------------------------
// fp32 -> (bf16 hi, bf16 lo) split conversion. grid.z picks one of nsrc inputs.
// ---------------------------------------------------------------------------
__global__ void __launch_bounds__(256) split_bf16_kernel(
    const float4* __restrict__ in0, const float4* __restrict__ in1,
    const float4* __restrict__ in2, const float4* __restrict__ in3,
    __nv_bfloat162* __restrict__ hi,
    __nv_bfloat162* __restrict__ lo,
    int n4)
{
    int i = blockIdx.x * blockDim.x + threadIdx.x;
    if (i >= n4) return;
    int z = blockIdx.z;
    const float4* in = (z == 0) ? in0 : (z == 1) ? in1 : (z == 2) ? in2 : in3;
    size_t o = (size_t)z * n4 + i;
    float4 v = in[i];
    uint32_t h0, l0, h1, l1;
    split_pack(v.x, v.y, h0, l0);
    split_pack(v.z, v.w, h1, l1);
    ((uint32_t*)hi)[2 * o]     = h0;
    ((uint32_t*)hi)[2 * o + 1] = h1;
    ((uint32_t*)lo)[2 * o]     = l0;
    ((uint32_t*)lo)[2 * o + 1] = l1;
}

// ---------------------------------------------------------------------------
// Split-bf16 GEMM via mma.sync, cp.async 2-stage pipelined.
// C[M,N] = A[M,K] * B[N,K]^T ;  C = Ahi*Bhi + Ahi*Blo + Alo*Bhi
// CTA: 128x128 tile, 256 threads = 8 warps (4 M x 2 N), warp tile 32x64.
// smem: 2 stages x (Ahi,Alo,Bhi,Blo)[128][64] bf16 = 2 x 64 KB.
// ---------------------------------------------------------------------------
#define TILE_BYTES 16384                  // 128*64*2
#define SA_HI 0
#define SA_LO (SA_HI + TILE_BYTES)
#define SB_HI (SA_LO + TILE_BYTES)
#define SB_LO (SB_HI + TILE_BYTES)
#define GSTAGE (4 * TILE_BYTES)           // 64 KB per stage
#define GSM_TOTAL (2 * GSTAGE)            // 128 KB

__global__ void __launch_bounds__(256) gemm_mma_kernel(
    const __nv_bfloat16* __restrict__ Ahi, const __nv_bfloat16* __restrict__ Alo,
    const __nv_bfloat16* __restrict__ B0h, const __nv_bfloat16* __restrict__ B0l,
    const __nv_bfloat16* __restrict__ B1h, const __nv_bfloat16* __restrict__ B1l,
    const __nv_bfloat16* __restrict__ B2h, const __nv_bfloat16* __restrict__ B2l,
    float* __restrict__ C,
    __nv_bfloat16* __restrict__ Qh, __nv_bfloat16* __restrict__ Ql,
    __nv_bfloat16* __restrict__ Kh, __nv_bfloat16* __restrict__ Kl,
    __nv_bfloat16* __restrict__ Vth, __nv_bfloat16* __restrict__ Vtl,
    int qkv)
{
    extern __shared__ char smem[];
    const uint32_t sbase = smem_u32(smem);

    const int tid  = threadIdx.x;
    const int wid  = tid >> 5;
    const int lane = tid & 31;
    const int warp_m = wid & 3;
    const int warp_n = wid >> 2;
    const int bn = blockIdx.x;
    const int bm = blockIdx.y;
    const int z  = blockIdx.z;

    const __nv_bfloat16* Bh = (z == 0) ? B0h : (z == 1) ? B1h : B2h;
    const __nv_bfloat16* Bl = (z == 0) ? B0l : (z == 1) ? B1l : B2l;

    float acc[2][8][4];
#pragma unroll
    for (int i = 0; i < 2; i++)
#pragma unroll
        for (int j = 0; j < 8; j++)
#pragma unroll
            for (int k = 0; k < 4; k++) acc[i][j][k] = 0.0f;

    const int lrow  = tid >> 1;
    const int lhalf = (tid & 1) * 64;

    const char* gAh = (const char*)(Ahi + (size_t)(bm * 128 + lrow) * DMODEL) + lhalf;
    const char* gAl = (const char*)(Alo + (size_t)(bm * 128 + lrow) * DMODEL) + lhalf;
    const char* gBh = (const char*)(Bh  + (size_t)(bn * 128 + lrow) * DMODEL) + lhalf;
    const char* gBl = (const char*)(Bl  + (size_t)(bn * 128 + lrow) * DMODEL) + lhalf;

    const int a_row16 = lane & 15;
    const int a_koff  = (lane >> 4) * 16;
    const int b_row16 = (lane & 7) | ((lane & 16) >> 1);
    const int b_koff  = ((lane >> 3) & 1) * 16;

    // per-thread staging addresses (4 x 16B per array)
    uint32_t stofs[4];
#pragma unroll
    for (int i = 0; i < 4; i++)
        stofs[i] = sw128((uint32_t)(lrow * 128 + lhalf + i * 16));

    // ---- prologue: stage chunk 0 ----
    {
#pragma unroll
        for (int i = 0; i < 4; i++) {
            cp16(sbase + SA_HI + stofs[i], gAh + i * 16);
            cp16(sbase + SA_LO + stofs[i], gAl + i * 16);
            cp16(sbase + SB_HI + stofs[i], gBh + i * 16);
            cp16(sbase + SB_LO + stofs[i], gBl + i * 16);
        }
        CP_COMMIT();
    }

    for (int t = 0; t < DMODEL / 64; t++) {
        // prefetch next chunk into the other stage
        if (t < DMODEL / 64 - 1) {
            const int gofs = (t + 1) * 128;
            const uint32_t sb = sbase + ((t + 1) & 1) * GSTAGE;
#pragma unroll
            for (int i = 0; i < 4; i++) {
                cp16(sb + SA_HI + stofs[i], gAh + gofs + i * 16);
                cp16(sb + SA_LO + stofs[i], gAl + gofs + i * 16);
                cp16(sb + SB_HI + stofs[i], gBh + gofs + i * 16);
                cp16(sb + SB_LO + stofs[i], gBl + gofs + i * 16);
            }
            CP_COMMIT();
            CP_WAIT(1);
        } else {
            CP_WAIT(0);
        }
        __syncthreads();

        const uint32_t cb = sbase + (t & 1) * GSTAGE;
#pragma unroll
        for (int k16 = 0; k16 < 4; k16++) {
            const int kb = k16 * 32;
            uint32_t ah[2][4], al[2][4];
#pragma unroll
            for (int mt = 0; mt < 2; mt++) {
                int r = warp_m * 32 + mt * 16 + a_row16;
                uint32_t off = sw128((uint32_t)(r * 128 + kb + a_koff));
                ldsm4(ah[mt], cb + SA_HI + off);
                ldsm4(al[mt], cb + SA_LO + off);
            }
#pragma unroll
            for (int np = 0; np < 4; np++) {
                int nr = warp_n * 64 + np * 16 + b_row16;
                uint32_t off = sw128((uint32_t)(nr * 128 + kb + b_koff));
                uint32_t bhf[4], blf[4];
                ldsm4(bhf, cb + SB_HI + off);
                ldsm4(blf, cb + SB_LO + off);
#pragma unroll
                for (int mt = 0; mt < 2; mt++) {
                    mma16816(acc[mt][2 * np],     ah[mt], bhf[0], bhf[1]);
                    mma16816(acc[mt][2 * np],     ah[mt], blf[0], blf[1]);
                    mma16816(acc[mt][2 * np],     al[mt], bhf[0], bhf[1]);
                    mma16816(acc[mt][2 * np + 1], ah[mt], bhf[2], bhf[3]);
                    mma16816(acc[mt][2 * np + 1], ah[mt], blf[2], blf[3]);
                    mma16816(acc[mt][2 * np + 1], al[mt], bhf[2], bhf[3]);
                }
            }
        }
        __syncthreads();
    }

    // ---- epilogue ----
    const int mode = qkv ? ((z == 2) ? 2 : 1) : 0;
    const int grp = lane >> 2;
    const int tig = lane & 3;
    __nv_bfloat16* Hp = (z == 0) ? Qh : Kh;
    __nv_bfloat16* Lp = (z == 0) ? Ql : Kl;

#pragma unroll
    for (int mt = 0; mt < 2; mt++) {
        int row = bm * 128 + warp_m * 32 + mt * 16 + grp;
#pragma unroll
        for (int nt = 0; nt < 8; nt++) {
            int col = bn * 128 + warp_n * 64 + nt * 8 + tig * 2;
            float v00 = acc[mt][nt][0], v01 = acc[mt][nt][1];
            float v10 = acc[mt][nt][2], v11 = acc[mt][nt][3];
            if (mode == 0) {
                *(float2*)(C + (size_t)row * DMODEL + col)       = make_float2(v00, v01);
                *(float2*)(C + (size_t)(row + 8) * DMODEL + col) = make_float2(v10, v11);
            } else if (mode == 1) {
                uint32_t h0, l0, h1, l1;
                split_pack(v00, v01, h0, l0);
                split_pack(v10, v11, h1, l1);
                *(uint32_t*)(Hp + (size_t)row * DMODEL + col)       = h0;
                *(uint32_t*)(Hp + (size_t)(row + 8) * DMODEL + col) = h1;
                *(uint32_t*)(Lp + (size_t)row * DMODEL + col)       = l0;
                *(uint32_t*)(Lp + (size_t)(row + 8) * DMODEL + col) = l1;
            } else {
                int bb = row >> 11;
                int tt = row & (SEQ - 1);
                size_t base0 = (size_t)(bb * DMODEL + col) * SEQ;
                size_t base1 = (size_t)(bb * DMODEL + col + 1) * SEQ;
                __nv_bfloat16 h00 = __float2bfloat16(v00);
                __nv_bfloat16 h01 = __float2bfloat16(v01);
                __nv_bfloat16 h10 = __float2bfloat16(v10);
                __nv_bfloat16 h11 = __float2bfloat16(v11);
                Vth[base0 + tt]     = h00;
                Vth[base1 + tt]     = h01;
                Vth[base0 + tt + 8] = h10;
                Vth[base1 + tt + 8] = h11;
                Vtl[base0 + tt]     = __float2bfloat16(v00 - __bfloat162float(h00));
                Vtl[base1 + tt]     = __float2bfloat16(v01 - __bfloat162float(h01));
                Vtl[base0 + tt + 8] = __float2bfloat16(v10 - __bfloat162float(h10));
                Vtl[base1 + tt + 8] = __float2bfloat16(v11 - __bfloat162float(h11));
            }
        }
    }
}

// ---------------------------------------------------------------------------
// Flash attention via mma.sync, cp.async 2-stage pipelined K/V.
// CTA: 64 q-rows x d=64, kv tiles of 64. 128 threads = 4 warps.
// smem: 2 stages x (Khi,Klo,Vhi,Vlo)[64][64] = 2 x 32 KB, + Q hi/lo 16 KB.
// ---------------------------------------------------------------------------
#define FA_TILE 8192
#define FA_KHI 0
#define FA_KLO (FA_KHI + FA_TILE)
#define FA_VHI (FA_KLO + FA_TILE)
#define FA_VLO (FA_VHI + FA_TILE)
#define FA_STAGE (4 * FA_TILE)            // 32 KB
#define FA_QHI (2 * FA_STAGE)             // 65536
#define FA_QLO (FA_QHI + FA_TILE)
#define FA_TOTAL (FA_QLO + FA_TILE)       // 81920

__global__ void __launch_bounds__(128) fa_mma_kernel(
    const __nv_bfloat16* __restrict__ Qhi, const __nv_bfloat16* __restrict__ Qlo,
    const __nv_bfloat16* __restrict__ Khi, const __nv_bfloat16* __restrict__ Klo,
    const __nv_bfloat16* __restrict__ Vthi, const __nv_bfloat16* __restrict__ Vtlo,
    float* __restrict__ O)
{
    extern __shared__ char smem[];
    const uint32_t sbase = smem_u32(smem);
    const int tid  = threadIdx.x;
    const int wid  = tid >> 5;
    const int lane = tid & 31;
    const int bq = blockIdx.x;
    const int bh = blockIdx.y;
    const int b  = bh >> 4;
    const int h  = bh & 15;

    const int grp = lane >> 2;
    const int tig = lane & 3;
    const int a_row16 = lane & 15;
    const int a_koff  = (lane >> 4) * 16;
    const int b_row16 = (lane & 7) | ((lane & 16) >> 1);
    const int b_koff  = ((lane >> 3) & 1) * 16;

    const char* gkh = (const char*)Khi + ((size_t)(b * SEQ) * DMODEL + h * 64) * 2;
    const char* gkl = (const char*)Klo + ((size_t)(b * SEQ) * DMODEL + h * 64) * 2;
    const char* gvh = (const char*)Vthi + ((size_t)bh * DHEAD * SEQ) * 2;
    const char* gvl = (const char*)Vtlo + ((size_t)bh * DHEAD * SEQ) * 2;

    // staging layout per thread: 4 iterations, each (row, 16B col)
    int srow[4], sc16[4];
    uint32_t sofs[4];
#pragma unroll
    for (int u = 0; u < 4; u++) {
        int f = u * 128 + tid;
        srow[u] = f >> 3;
        sc16[u] = (f & 7) * 16;
        sofs[u] = sw128((uint32_t)(srow[u] * 128 + sc16[u]));
    }

    // ---- stage Q (hi+lo) via cp.async ----
    {
        const char* gqh = (const char*)Qhi + ((size_t)(b * SEQ + bq * 64) * DMODEL + h * 64) * 2;
        const char* gql = (const char*)Qlo + ((size_t)(b * SEQ + bq * 64) * DMODEL + h * 64) * 2;
#pragma unroll
        for (int u = 0; u < 4; u++) {
            cp16(sbase + FA_QHI + sofs[u], gqh + (size_t)srow[u] * DMODEL * 2 + sc16[u]);
            cp16(sbase + FA_QLO + sofs[u], gql + (size_t)srow[u] * DMODEL * 2 + sc16[u]);
        }
    }
    // ---- stage K/V tile 0 ----
    {
        const uint32_t sb = sbase;
#pragma unroll
        for (int u = 0; u < 4; u++) {
            size_t ko = ((size_t)srow[u] * DMODEL) * 2 + sc16[u];
            cp16(sb + FA_KHI + sofs[u], gkh + ko);
            cp16(sb + FA_KLO + sofs[u], gkl + ko);
            size_t vo = ((size_t)srow[u] * SEQ) * 2 + sc16[u];
            cp16(sb + FA_VHI + sofs[u], gvh + vo);
            cp16(sb + FA_VLO + sofs[u], gvl + vo);
        }
        CP_COMMIT();
    }

    float oacc[8][4];
#pragma unroll
    for (int i = 0; i < 8; i++)
#pragma unroll
        for (int j = 0; j < 4; j++) oacc[i][j] = 0.0f;
    float m0 = -1e30f, m1 = -1e30f, l0 = 0.0f, l1 = 0.0f;

    const int qrow0 = wid * 16 + grp;

    for (int kb = 0; kb <= bq; kb++) {
        // prefetch next K/V tile
        if (kb < bq) {
            const uint32_t sb = sbase + ((kb + 1) & 1) * FA_STAGE;
#pragma unroll
            for (int u = 0; u < 4; u++) {
                size_t ko = ((size_t)((kb + 1) * 64 + srow[u]) * DMODEL) * 2 + sc16[u];
                cp16(sb + FA_KHI + sofs[u], gkh + ko);
                cp16(sb + FA_KLO + sofs[u], gkl + ko);
                size_t vo = ((size_t)srow[u] * SEQ + (kb + 1) * 64) * 2 + sc16[u];
                cp16(sb + FA_VHI + sofs[u], gvh + vo);
                cp16(sb + FA_VLO + sofs[u], gvl + vo);
            }
            CP_COMMIT();
            CP_WAIT(1);
        } else {
            CP_WAIT(0);
        }
        __syncthreads();

        const uint32_t cb = sbase + (kb & 1) * FA_STAGE;

        // ---- S = Q K^T (3-term split) ----
        float sacc[8][4];
#pragma unroll
        for (int i = 0; i < 8; i++)
#pragma unroll
            for (int j = 0; j < 4; j++) sacc[i][j] = 0.0f;

#pragma unroll
        for (int k16 = 0; k16 < 4; k16++) {
            uint32_t ah[4], al[4];
            uint32_t aoff = sw128((uint32_t)((wid * 16 + a_row16) * 128 + k16 * 32 + a_koff));
            ldsm4(ah, sbase + FA_QHI + aoff);
            ldsm4(al, sbase + FA_QLO + aoff);
#pragma unroll
            for (int np = 0; np < 4; np++) {
                uint32_t boff = sw128((uint32_t)((np * 16 + b_row16) * 128 + k16 * 32 + b_koff));
                uint32_t bhf[4], blf[4];
                ldsm4(bhf, cb + FA_KHI + boff);
                ldsm4(blf, cb + FA_KLO + boff);
                mma16816(sacc[2 * np],     ah, bhf[0], bhf[1]);
                mma16816(sacc[2 * np],     ah, blf[0], blf[1]);
                mma16816(sacc[2 * np],     al, bhf[0], bhf[1]);
                mma16816(sacc[2 * np + 1], ah, bhf[2], bhf[3]);
                mma16816(sacc[2 * np + 1], ah, blf[2], blf[3]);
                mma16816(sacc[2 * np + 1], al, bhf[2], bhf[3]);
            }
        }

        // ---- scale + causal mask ----
        const float scale = 0.125f;
        const bool diag = (kb == bq);
#pragma unroll
        for (int nt = 0; nt < 8; nt++) {
            int c0 = nt * 8 + tig * 2;
            sacc[nt][0] *= scale; sacc[nt][1] *= scale;
            sacc[nt][2] *= scale; sacc[nt][3] *= scale;
            if (diag) {
                if (c0     > qrow0)     sacc[nt][0] = -1e30f;
                if (c0 + 1 > qrow0)     sacc[nt][1] = -1e30f;
                if (c0     > qrow0 + 8) sacc[nt][2] = -1e30f;
                if (c0 + 1 > qrow0 + 8) sacc[nt][3] = -1e30f;
            }
        }

        // ---- online softmax ----
        float rm0 = -1e30f, rm1 = -1e30f;
#pragma unroll
        for (int nt = 0; nt < 8; nt++) {
            rm0 = fmaxf(rm0, fmaxf(sacc[nt][0], sacc[nt][1]));
            rm1 = fmaxf(rm1, fmaxf(sacc[nt][2], sacc[nt][3]));
        }
        rm0 = fmaxf(rm0, __shfl_xor_sync(0xffffffffu, rm0, 1));
        rm0 = fmaxf(rm0, __shfl_xor_sync(0xffffffffu, rm0, 2));
        rm1 = fmaxf(rm1, __shfl_xor_sync(0xffffffffu, rm1, 1));
        rm1 = fmaxf(rm1, __shfl_xor_sync(0xffffffffu, rm1, 2));

        float mn0 = fmaxf(m0, rm0), mn1 = fmaxf(m1, rm1);
        float corr0 = __expf(m0 - mn0), corr1 = __expf(m1 - mn1);
        float rs0 = 0.0f, rs1 = 0.0f;
#pragma unroll
        for (int nt = 0; nt < 8; nt++) {
            sacc[nt][0] = __expf(sacc[nt][0] - mn0);
            sacc[nt][1] = __expf(sacc[nt][1] - mn0);
            sacc[nt][2] = __expf(sacc[nt][2] - mn1);
            sacc[nt][3] = __expf(sacc[nt][3] - mn1);
            rs0 += sacc[nt][0] + sacc[nt][1];
            rs1 += sacc[nt][2] + sacc[nt][3];
        }
        rs0 += __shfl_xor_sync(0xffffffffu, rs0, 1);
        rs0 += __shfl_xor_sync(0xffffffffu, rs0, 2);
        rs1 += __shfl_xor_sync(0xffffffffu, rs1, 1);
        rs1 += __shfl_xor_sync(0xffffffffu, rs1, 2);

        l0 = l0 * corr0 + rs0;
        l1 = l1 * corr1 + rs1;
        m0 = mn0; m1 = mn1;
#pragma unroll
        for (int nt = 0; nt < 8; nt++) {
            oacc[nt][0] *= corr0; oacc[nt][1] *= corr0;
            oacc[nt][2] *= corr1; oacc[nt][3] *= corr1;
        }

        // ---- O += P V (3-term split; P from registers) ----
#pragma unroll
        for (int j = 0; j < 4; j++) {
            uint32_t ph[4], pl[4];
            split_pack(sacc[2 * j][0],     sacc[2 * j][1],     ph[0], pl[0]);
            split_pack(sacc[2 * j][2],     sacc[2 * j][3],     ph[1], pl[1]);
            split_pack(sacc[2 * j + 1][0], sacc[2 * j + 1][1], ph[2], pl[2]);
            split_pack(sacc[2 * j + 1][2], sacc[2 * j + 1][3], ph[3], pl[3]);
#pragma unroll
            for (int nd = 0; nd < 4; nd++) {
                uint32_t boff = sw128((uint32_t)((nd * 16 + b_row16) * 128 + j * 32 + b_koff));
                uint32_t vh[4], vl[4];
                ldsm4(vh, cb + FA_VHI + boff);
                ldsm4(vl, cb + FA_VLO + boff);
                mma16816(oacc[2 * nd],     ph, vh[0], vh[1]);
                mma16816(oacc[2 * nd],     ph, vl[0], vl[1]);
                mma16816(oacc[2 * nd],     pl, vh[0], vh[1]);
                mma16816(oacc[2 * nd + 1], ph, vh[2], vh[3]);
                mma16816(oacc[2 * nd + 1], ph, vl[2], vl[3]);
                mma16816(oacc[2 * nd + 1], pl, vh[2], vh[3]);
            }
        }
        __syncthreads();
    }

    // ---- epilogue ----
    float inv0 = 1.0f / l0;
    float inv1 = 1.0f / l1;
    float* Ob = O + ((size_t)(b * SEQ + bq * 64 + wid * 16 + grp)) * DMODEL + h * 64;
#pragma unroll
    for (int nt = 0; nt < 8; nt++) {
        int col = nt * 8 + tig * 2;
        *(float2*)(Ob + col) = make_float2(oacc[nt][0] * inv0, oacc[nt][1] * inv0);
        *(float2*)(Ob + (size_t)8 * DMODEL + col) = make_float2(oacc[nt][2] * inv1, oacc[nt][3] * inv1);
    }
}

// ---------------------------------------------------------------------------
// Launch
// ---------------------------------------------------------------------------
extern "C" void kernel_launch(void* const* d_in, const int* in_sizes, int n_in,
                              void* d_out, int out_size)
{
    const float* x  = (const float*)d_in[0];
    const float* Wq = (const float*)d_in[1];
    const float* Wk = (const float*)d_in[2];
    const float* Wv = (const float*)d_in[3];
    const float* Wo = (const float*)d_in[4];
    float* out = (float*)d_out;

    float* Ob;
    cudaGetSymbolAddress((void**)&Ob, g_O);

    __nv_bfloat16 *xhi, *xlo, *ohi, *olo, *whi, *wlo;
    __nv_bfloat16 *Qh, *Ql, *Kh, *Kl, *Vth, *Vtl;
    cudaGetSymbolAddress((void**)&xhi, g_xhi);
    cudaGetSymbolAddress((void**)&xlo, g_xlo);
    cudaGetSymbolAddress((void**)&ohi, g_ohi);
    cudaGetSymbolAddress((void**)&olo, g_olo);
    cudaGetSymbolAddress((void**)&whi, g_whi);
    cudaGetSymbolAddress((void**)&wlo, g_wlo);
    cudaGetSymbolAddress((void**)&Qh,  g_Qhi);
    cudaGetSymbolAddress((void**)&Ql,  g_Qlo);
    cudaGetSymbolAddress((void**)&Kh,  g_Khi);
    cudaGetSymbolAddress((void**)&Kl,  g_Klo);
    cudaGetSymbolAddress((void**)&Vth, g_Vthi);
    cudaGetSymbolAddress((void**)&Vtl, g_Vtlo);

    const int WN  = DMODEL * DMODEL;
    const int xn4 = (MT * DMODEL) / 4;
    const int wn4 = WN / 4;

    // x split (1 input), weight splits (4 inputs via grid.z)
    dim3 xsGrid((xn4 + 255) / 256, 1, 1);
    split_bf16_kernel<<<xsGrid, 256>>>(
        (const float4*)x, nullptr, nullptr, nullptr,
        (__nv_bfloat162*)xhi, (__nv_bfloat162*)xlo, xn4);
    dim3 wsGrid((wn4 + 255) / 256, 1, 4);
    split_bf16_kernel<<<wsGrid, 256>>>(
        (const float4*)Wq, (const float4*)Wk, (const float4*)Wv, (const float4*)Wo,
        (__nv_bfloat162*)whi, (__nv_bfloat162*)wlo, wn4);

    cudaFuncSetAttribute(gemm_mma_kernel,
                         cudaFuncAttributeMaxDynamicSharedMemorySize, GSM_TOTAL);
    cudaFuncSetAttribute(fa_mma_kernel,
                         cudaFuncAttributeMaxDynamicSharedMemorySize, FA_TOTAL);

    // QKV projections: z=0 -> Q split, z=1 -> K split, z=2 -> V split transposed
    dim3 qkvGrid(DMODEL / 128, MT / 128, 3);
    gemm_mma_kernel<<<qkvGrid, 256, GSM_TOTAL>>>(
        xhi, xlo,
        whi + 0 * (size_t)WN, wlo + 0 * (size_t)WN,
        whi + 1 * (size_t)WN, wlo + 1 * (size_t)WN,
        whi + 2 * (size_t)WN, wlo + 2 * (size_t)WN,
        nullptr, Qh, Ql, Kh, Kl, Vth, Vtl, 1);

    // Flash attention (tensor-core, pipelined)
    dim3 faGrid(SEQ / 64, BATCH * NHEADS);
    fa_mma_kernel<<<faGrid, 128, FA_TOTAL>>>(Qh, Ql, Kh, Kl, Vth, Vtl, Ob);

    // O projection
    dim3 osGrid((xn4 + 255) / 256, 1, 1);
    split_bf16_kernel<<<osGrid, 256>>>(
        (const float4*)Ob, nullptr, nullptr, nullptr,
        (__nv_bfloat162*)ohi, (__nv_bfloat162*)olo, xn4);
    dim3 oGrid(DMODEL / 128, MT / 128, 1);
    gemm_mma_kernel<<<oGrid, 256, GSM_TOTAL>>>(
        ohi, olo,
        whi + 3 * (size_t)WN, wlo + 3 * (size_t)WN,
        whi + 3 * (size_t)WN, wlo + 3 * (size_t)WN,
        whi + 3 * (size_t)WN, wlo + 3 * (size_t)WN,
        out, nullptr, nullptr, nullptr, nullptr, nullptr, nullptr, 0);
}

// round 6
// speedup vs baseline: 2.9984x; 1.0529x over previous
#include <cuda_runtime.h>
#include <cuda_bf16.h>
#include <cstdint>

// Problem constants
#define BATCH   2
#define SEQ     2048
#define DMODEL  1024
#define NHEADS  16
#define DHEAD   64
#define MT      (BATCH * SEQ)        // 4096 rows

// ---------------------------------------------------------------------------
// Scratch (device globals: no cudaMalloc allowed)
// ---------------------------------------------------------------------------
__device__ __nv_bfloat16 g_xhi[MT * DMODEL];
__device__ __nv_bfloat16 g_xlo[MT * DMODEL];
__device__ __nv_bfloat16 g_ohi[MT * DMODEL];
__device__ __nv_bfloat16 g_olo[MT * DMODEL];
__device__ __nv_bfloat16 g_whi[4][DMODEL * DMODEL];
__device__ __nv_bfloat16 g_wlo[4][DMODEL * DMODEL];

__device__ __nv_bfloat16 g_Qhi[MT * DMODEL];
__device__ __nv_bfloat16 g_Qlo[MT * DMODEL];
__device__ __nv_bfloat16 g_Khi[MT * DMODEL];
__device__ __nv_bfloat16 g_Klo[MT * DMODEL];
__device__ __nv_bfloat16 g_Vthi[MT * DMODEL];   // [b][h][d][t]
__device__ __nv_bfloat16 g_Vtlo[MT * DMODEL];

// ---------------------------------------------------------------------------
// Helpers (base ISA only — harness PTX target is compute_103, no tcgen05)
// ---------------------------------------------------------------------------
__device__ __forceinline__ uint32_t smem_u32(const void* p) {
    uint32_t a;
    asm("{ .reg .u64 t; cvta.to.shared.u64 t, %1; cvt.u32.u64 %0, t; }"
        : "=r"(a) : "l"(p));
    return a;
}

__device__ __forceinline__ uint32_t sw128(uint32_t off) {
    return off ^ ((off >> 3) & 0x70);
}

__device__ __forceinline__ void ldsm4(uint32_t* r, uint32_t addr) {
    asm volatile("ldmatrix.sync.aligned.m8n8.x4.shared.b16 {%0,%1,%2,%3}, [%4];"
        : "=r"(r[0]), "=r"(r[1]), "=r"(r[2]), "=r"(r[3]) : "r"(addr));
}

__device__ __forceinline__ void mma16816(float* c, const uint32_t* a,
                                         uint32_t b0, uint32_t b1) {
    asm volatile(
        "mma.sync.aligned.m16n8k16.row.col.f32.bf16.bf16.f32 "
        "{%0,%1,%2,%3}, {%4,%5,%6,%7}, {%8,%9}, {%0,%1,%2,%3};"
        : "+f"(c[0]), "+f"(c[1]), "+f"(c[2]), "+f"(c[3])
        : "r"(a[0]), "r"(a[1]), "r"(a[2]), "r"(a[3]), "r"(b0), "r"(b1));
}

__device__ __forceinline__ void cp16(uint32_t dst, const void* src) {
    asm volatile("cp.async.cg.shared.global [%0], [%1], 16;"
                 :: "r"(dst), "l"(src));
}
#define CP_COMMIT()  asm volatile("cp.async.commit_group;")
#define CP_WAIT(N)   asm volatile("cp.async.wait_group %0;" :: "n"(N))

// split two floats into packed bf16 hi/lo pairs
__device__ __forceinline__ void split_pack(float x, float y, uint32_t& hi, uint32_t& lo) {
    __nv_bfloat16 hx = __float2bfloat16(x), hy = __float2bfloat16(y);
    __nv_bfloat16 lx = __float2bfloat16(x - __bfloat162float(hx));
    __nv_bfloat16 ly = __float2bfloat16(y - __bfloat162float(hy));
    __nv_bfloat162 h2 = __halves2bfloat162(hx, hy);
    __nv_bfloat162 l2 = __halves2bfloat162(lx, ly);
    hi = *(uint32_t*)&h2;
    lo = *(uint32_t*)&l2;
}

// ---------------------------------------------------------------------------
// fp32 -> (bf16 hi, bf16 lo) split conversion. grid.z picks one of the inputs.
// ---------------------------------------------------------------------------
__global__ void __launch_bounds__(256) split_bf16_kernel(
    const float4* __restrict__ in0, const float4* __restrict__ in1,
    const float4* __restrict__ in2, const float4* __restrict__ in3,
    __nv_bfloat162* __restrict__ hi,
    __nv_bfloat162* __restrict__ lo,
    int n4)
{
    int i = blockIdx.x * blockDim.x + threadIdx.x;
    if (i >= n4) return;
    int z = blockIdx.z;
    const float4* in = (z == 0) ? in0 : (z == 1) ? in1 : (z == 2) ? in2 : in3;
    size_t o = (size_t)z * n4 + i;
    float4 v = in[i];
    uint32_t h0, l0, h1, l1;
    split_pack(v.x, v.y, h0, l0);
    split_pack(v.z, v.w, h1, l1);
    ((uint32_t*)hi)[2 * o]     = h0;
    ((uint32_t*)hi)[2 * o + 1] = h1;
    ((uint32_t*)lo)[2 * o]     = l0;
    ((uint32_t*)lo)[2 * o + 1] = l1;
}

// ---------------------------------------------------------------------------
// Split-bf16 GEMM via mma.sync, cp.async 2-stage pipelined.
// C[M,N] = A[M,K] * B[N,K]^T ;  C = Ahi*Bhi + Ahi*Blo + Alo*Bhi
// CTA: 128x128 tile, 512 threads = 16 warps (4 M x 4 N), warp tile 32x32.
// smem: 2 stages x (Ahi,Alo,Bhi,Blo)[128][64] bf16 = 2 x 64 KB.
// ---------------------------------------------------------------------------
#define TILE_BYTES 16384                  // 128*64*2
#define SA_HI 0
#define SA_LO (SA_HI + TILE_BYTES)
#define SB_HI (SA_LO + TILE_BYTES)
#define SB_LO (SB_HI + TILE_BYTES)
#define GSTAGE (4 * TILE_BYTES)           // 64 KB per stage
#define GSM_TOTAL (2 * GSTAGE)            // 128 KB

__global__ void __launch_bounds__(512) gemm_mma_kernel(
    const __nv_bfloat16* __restrict__ Ahi, const __nv_bfloat16* __restrict__ Alo,
    const __nv_bfloat16* __restrict__ B0h, const __nv_bfloat16* __restrict__ B0l,
    const __nv_bfloat16* __restrict__ B1h, const __nv_bfloat16* __restrict__ B1l,
    const __nv_bfloat16* __restrict__ B2h, const __nv_bfloat16* __restrict__ B2l,
    float* __restrict__ C,
    __nv_bfloat16* __restrict__ Qh, __nv_bfloat16* __restrict__ Ql,
    __nv_bfloat16* __restrict__ Kh, __nv_bfloat16* __restrict__ Kl,
    __nv_bfloat16* __restrict__ Vth, __nv_bfloat16* __restrict__ Vtl,
    int qkv)
{
    extern __shared__ char smem[];
    const uint32_t sbase = smem_u32(smem);

    const int tid  = threadIdx.x;
    const int wid  = tid >> 5;            // 0..15
    const int lane = tid & 31;
    const int warp_m = wid & 3;           // 0..3 (x32 rows)
    const int warp_n = wid >> 2;          // 0..3 (x32 cols)
    const int bn = blockIdx.x;
    const int bm = blockIdx.y;
    const int z  = blockIdx.z;

    const __nv_bfloat16* Bh = (z == 0) ? B0h : (z == 1) ? B1h : B2h;
    const __nv_bfloat16* Bl = (z == 0) ? B0l : (z == 1) ? B1l : B2l;

    float acc[2][4][4];
#pragma unroll
    for (int i = 0; i < 2; i++)
#pragma unroll
        for (int j = 0; j < 4; j++)
#pragma unroll
            for (int k = 0; k < 4; k++) acc[i][j][k] = 0.0f;

    // staging: thread -> row=tid>>2 (0..127), col-bytes (tid&3)*32; 2 x 16B per array
    const int trow = tid >> 2;
    const int tcol = (tid & 3) * 32;

    const char* gAh = (const char*)(Ahi + (size_t)(bm * 128 + trow) * DMODEL) + tcol;
    const char* gAl = (const char*)(Alo + (size_t)(bm * 128 + trow) * DMODEL) + tcol;
    const char* gBh = (const char*)(Bh  + (size_t)(bn * 128 + trow) * DMODEL) + tcol;
    const char* gBl = (const char*)(Bl  + (size_t)(bn * 128 + trow) * DMODEL) + tcol;

    uint32_t stofs[2];
#pragma unroll
    for (int i = 0; i < 2; i++)
        stofs[i] = sw128((uint32_t)(trow * 128 + tcol + i * 16));

    const int a_row16 = lane & 15;
    const int a_koff  = (lane >> 4) * 16;
    const int b_row16 = (lane & 7) | ((lane & 16) >> 1);
    const int b_koff  = ((lane >> 3) & 1) * 16;

    // ---- prologue: stage chunk 0 ----
#pragma unroll
    for (int i = 0; i < 2; i++) {
        cp16(sbase + SA_HI + stofs[i], gAh + i * 16);
        cp16(sbase + SA_LO + stofs[i], gAl + i * 16);
        cp16(sbase + SB_HI + stofs[i], gBh + i * 16);
        cp16(sbase + SB_LO + stofs[i], gBl + i * 16);
    }
    CP_COMMIT();

    for (int t = 0; t < DMODEL / 64; t++) {
        if (t < DMODEL / 64 - 1) {
            const int gofs = (t + 1) * 128;
            const uint32_t sb = sbase + ((t + 1) & 1) * GSTAGE;
#pragma unroll
            for (int i = 0; i < 2; i++) {
                cp16(sb + SA_HI + stofs[i], gAh + gofs + i * 16);
                cp16(sb + SA_LO + stofs[i], gAl + gofs + i * 16);
                cp16(sb + SB_HI + stofs[i], gBh + gofs + i * 16);
                cp16(sb + SB_LO + stofs[i], gBl + gofs + i * 16);
            }
            CP_COMMIT();
            CP_WAIT(1);
        } else {
            CP_WAIT(0);
        }
        __syncthreads();

        const uint32_t cb = sbase + (t & 1) * GSTAGE;
#pragma unroll
        for (int k16 = 0; k16 < 4; k16++) {
            const int kb = k16 * 32;
            uint32_t ah[2][4], al[2][4];
#pragma unroll
            for (int mt = 0; mt < 2; mt++) {
                int r = warp_m * 32 + mt * 16 + a_row16;
                uint32_t off = sw128((uint32_t)(r * 128 + kb + a_koff));
                ldsm4(ah[mt], cb + SA_HI + off);
                ldsm4(al[mt], cb + SA_LO + off);
            }
#pragma unroll
            for (int np = 0; np < 2; np++) {
                int nr = warp_n * 32 + np * 16 + b_row16;
                uint32_t off = sw128((uint32_t)(nr * 128 + kb + b_koff));
                uint32_t bhf[4], blf[4];
                ldsm4(bhf, cb + SB_HI + off);
                ldsm4(blf, cb + SB_LO + off);
#pragma unroll
                for (int mt = 0; mt < 2; mt++) {
                    mma16816(acc[mt][2 * np],     ah[mt], bhf[0], bhf[1]);
                    mma16816(acc[mt][2 * np],     ah[mt], blf[0], blf[1]);
                    mma16816(acc[mt][2 * np],     al[mt], bhf[0], bhf[1]);
                    mma16816(acc[mt][2 * np + 1], ah[mt], bhf[2], bhf[3]);
                    mma16816(acc[mt][2 * np + 1], ah[mt], blf[2], blf[3]);
                    mma16816(acc[mt][2 * np + 1], al[mt], bhf[2], bhf[3]);
                }
            }
        }
        __syncthreads();
    }

    // ---- epilogue ----
    const int mode = qkv ? ((z == 2) ? 2 : 1) : 0;
    const int grp = lane >> 2;
    const int tig = lane & 3;
    __nv_bfloat16* Hp = (z == 0) ? Qh : Kh;
    __nv_bfloat16* Lp = (z == 0) ? Ql : Kl;

#pragma unroll
    for (int mt = 0; mt < 2; mt++) {
        int row = bm * 128 + warp_m * 32 + mt * 16 + grp;
#pragma unroll
        for (int nt = 0; nt < 4; nt++) {
            int col = bn * 128 + warp_n * 32 + nt * 8 + tig * 2;
            float v00 = acc[mt][nt][0], v01 = acc[mt][nt][1];
            float v10 = acc[mt][nt][2], v11 = acc[mt][nt][3];
            if (mode == 0) {
                *(float2*)(C + (size_t)row * DMODEL + col)       = make_float2(v00, v01);
                *(float2*)(C + (size_t)(row + 8) * DMODEL + col) = make_float2(v10, v11);
            } else if (mode == 1) {
                uint32_t h0, l0, h1, l1;
                split_pack(v00, v01, h0, l0);
                split_pack(v10, v11, h1, l1);
                *(uint32_t*)(Hp + (size_t)row * DMODEL + col)       = h0;
                *(uint32_t*)(Hp + (size_t)(row + 8) * DMODEL + col) = h1;
                *(uint32_t*)(Lp + (size_t)row * DMODEL + col)       = l0;
                *(uint32_t*)(Lp + (size_t)(row + 8) * DMODEL + col) = l1;
            } else {
                int bb = row >> 11;
                int tt = row & (SEQ - 1);
                size_t base0 = (size_t)(bb * DMODEL + col) * SEQ;
                size_t base1 = (size_t)(bb * DMODEL + col + 1) * SEQ;
                __nv_bfloat16 h00 = __float2bfloat16(v00);
                __nv_bfloat16 h01 = __float2bfloat16(v01);
                __nv_bfloat16 h10 = __float2bfloat16(v10);
                __nv_bfloat16 h11 = __float2bfloat16(v11);
                Vth[base0 + tt]     = h00;
                Vth[base1 + tt]     = h01;
                Vth[base0 + tt + 8] = h10;
                Vth[base1 + tt + 8] = h11;
                Vtl[base0 + tt]     = __float2bfloat16(v00 - __bfloat162float(h00));
                Vtl[base1 + tt]     = __float2bfloat16(v01 - __bfloat162float(h01));
                Vtl[base0 + tt + 8] = __float2bfloat16(v10 - __bfloat162float(h10));
                Vtl[base1 + tt + 8] = __float2bfloat16(v11 - __bfloat162float(h11));
            }
        }
    }
}

// ---------------------------------------------------------------------------
// Flash attention via mma.sync, cp.async 2-stage pipelined K/V.
// CTA: 128 q-rows x d=64, kv tiles of 64. 256 threads = 8 warps (16 q-rows each).
// smem: 2 stages x (Khi,Klo,Vhi,Vlo)[64][64] = 2 x 32 KB, + Q hi/lo 32 KB = 96 KB.
// Writes split-bf16 O directly.
// ---------------------------------------------------------------------------
#define FA_TILE 8192
#define FA_KHI 0
#define FA_KLO (FA_KHI + FA_TILE)
#define FA_VHI (FA_KLO + FA_TILE)
#define FA_VLO (FA_VHI + FA_TILE)
#define FA_STAGE (4 * FA_TILE)            // 32 KB
#define FA_QHI (2 * FA_STAGE)             // 65536
#define FA_QLO (FA_QHI + 2 * FA_TILE)     // Q tile is 128x128B = 16 KB each
#define FA_TOTAL (FA_QLO + 2 * FA_TILE)   // 98304

__global__ void __launch_bounds__(256) fa_mma_kernel(
    const __nv_bfloat16* __restrict__ Qhi, const __nv_bfloat16* __restrict__ Qlo,
    const __nv_bfloat16* __restrict__ Khi, const __nv_bfloat16* __restrict__ Klo,
    const __nv_bfloat16* __restrict__ Vthi, const __nv_bfloat16* __restrict__ Vtlo,
    __nv_bfloat16* __restrict__ Ohi, __nv_bfloat16* __restrict__ Olo)
{
    extern __shared__ char smem[];
    const uint32_t sbase = smem_u32(smem);
    const int tid  = threadIdx.x;
    const int wid  = tid >> 5;           // 0..7
    const int lane = tid & 31;
    const int bq = (int)gridDim.x - 1 - (int)blockIdx.x;   // longest first (LPT)
    const int bh = blockIdx.y;
    const int b  = bh >> 4;
    const int h  = bh & 15;

    const int grp = lane >> 2;
    const int tig = lane & 3;
    const int a_row16 = lane & 15;
    const int a_koff  = (lane >> 4) * 16;
    const int b_row16 = (lane & 7) | ((lane & 16) >> 1);
    const int b_koff  = ((lane >> 3) & 1) * 16;

    const char* gkh = (const char*)Khi + ((size_t)(b * SEQ) * DMODEL + h * 64) * 2;
    const char* gkl = (const char*)Klo + ((size_t)(b * SEQ) * DMODEL + h * 64) * 2;
    const char* gvh = (const char*)Vthi + ((size_t)bh * DHEAD * SEQ) * 2;
    const char* gvl = (const char*)Vtlo + ((size_t)bh * DHEAD * SEQ) * 2;

    // K/V staging: row = tid>>2 (0..63), col-bytes (tid&3)*32; 2 x 16B per array
    const int krow = tid >> 2;
    const int kcol = (tid & 3) * 32;
    uint32_t kofs[2];
#pragma unroll
    for (int i = 0; i < 2; i++)
        kofs[i] = sw128((uint32_t)(krow * 128 + kcol + i * 16));

    // ---- stage Q (128 rows, hi+lo) + K/V tile 0 in one cp.async group ----
    {
        const char* gqh = (const char*)Qhi + ((size_t)(b * SEQ + bq * 128) * DMODEL + h * 64) * 2;
        const char* gql = (const char*)Qlo + ((size_t)(b * SEQ + bq * 128) * DMODEL + h * 64) * 2;
#pragma unroll
        for (int u = 0; u < 4; u++) {
            int f = u * 256 + tid;
            int qrow = f >> 3;
            int qc   = (f & 7) * 16;
            uint32_t qo = sw128((uint32_t)(qrow * 128 + qc));
            cp16(sbase + FA_QHI + qo, gqh + (size_t)qrow * DMODEL * 2 + qc);
            cp16(sbase + FA_QLO + qo, gql + (size_t)qrow * DMODEL * 2 + qc);
        }
#pragma unroll
        for (int i = 0; i < 2; i++) {
            size_t ko = ((size_t)krow * DMODEL) * 2 + kcol + i * 16;
            cp16(sbase + FA_KHI + kofs[i], gkh + ko);
            cp16(sbase + FA_KLO + kofs[i], gkl + ko);
            size_t vo = ((size_t)krow * SEQ) * 2 + kcol + i * 16;
            cp16(sbase + FA_VHI + kofs[i], gvh + vo);
            cp16(sbase + FA_VLO + kofs[i], gvl + vo);
        }
        CP_COMMIT();
    }

    float oacc[8][4];
#pragma unroll
    for (int i = 0; i < 8; i++)
#pragma unroll
        for (int j = 0; j < 4; j++) oacc[i][j] = 0.0f;
    float m0 = -1e30f, m1 = -1e30f, l0 = 0.0f, l1 = 0.0f;

    const int qg0 = bq * 128 + wid * 16 + grp;     // global q row of r0
    const int nkv = 2 * bq + 2;

    for (int kb = 0; kb < nkv; kb++) {
        if (kb < nkv - 1) {
            const uint32_t sb = sbase + ((kb + 1) & 1) * FA_STAGE;
#pragma unroll
            for (int i = 0; i < 2; i++) {
                size_t ko = ((size_t)((kb + 1) * 64 + krow) * DMODEL) * 2 + kcol + i * 16;
                cp16(sb + FA_KHI + kofs[i], gkh + ko);
                cp16(sb + FA_KLO + kofs[i], gkl + ko);
                size_t vo = ((size_t)krow * SEQ + (kb + 1) * 64) * 2 + kcol + i * 16;
                cp16(sb + FA_VHI + kofs[i], gvh + vo);
                cp16(sb + FA_VLO + kofs[i], gvl + vo);
            }
            CP_COMMIT();
            CP_WAIT(1);
        } else {
            CP_WAIT(0);
        }
        __syncthreads();

        const uint32_t cb = sbase + (kb & 1) * FA_STAGE;

        // ---- S = Q K^T (3-term split) ----
        float sacc[8][4];
#pragma unroll
        for (int i = 0; i < 8; i++)
#pragma unroll
            for (int j = 0; j < 4; j++) sacc[i][j] = 0.0f;

#pragma unroll
        for (int k16 = 0; k16 < 4; k16++) {
            uint32_t ah[4], al[4];
            uint32_t aoff = sw128((uint32_t)((wid * 16 + a_row16) * 128 + k16 * 32 + a_koff));
            ldsm4(ah, sbase + FA_QHI + aoff);
            ldsm4(al, sbase + FA_QLO + aoff);
#pragma unroll
            for (int np = 0; np < 4; np++) {
                uint32_t boff = sw128((uint32_t)((np * 16 + b_row16) * 128 + k16 * 32 + b_koff));
                uint32_t bhf[4], blf[4];
                ldsm4(bhf, cb + FA_KHI + boff);
                ldsm4(blf, cb + FA_KLO + boff);
                mma16816(sacc[2 * np],     ah, bhf[0], bhf[1]);
                mma16816(sacc[2 * np],     ah, blf[0], blf[1]);
                mma16816(sacc[2 * np],     al, bhf[0], bhf[1]);
                mma16816(sacc[2 * np + 1], ah, bhf[2], bhf[3]);
                mma16816(sacc[2 * np + 1], ah, blf[2], blf[3]);
                mma16816(sacc[2 * np + 1], al, bhf[2], bhf[3]);
            }
        }

        // ---- scale + causal mask (global positions; only last 2 tiles) ----
        const float scale = 0.125f;
        const bool need_mask = (kb >= 2 * bq);
#pragma unroll
        for (int nt = 0; nt < 8; nt++) {
            sacc[nt][0] *= scale; sacc[nt][1] *= scale;
            sacc[nt][2] *= scale; sacc[nt][3] *= scale;
            if (need_mask) {
                int c = kb * 64 + nt * 8 + tig * 2;
                if (c     > qg0)     sacc[nt][0] = -1e30f;
                if (c + 1 > qg0)     sacc[nt][1] = -1e30f;
                if (c     > qg0 + 8) sacc[nt][2] = -1e30f;
                if (c + 1 > qg0 + 8) sacc[nt][3] = -1e30f;
            }
        }

        // ---- online softmax ----
        float rm0 = -1e30f, rm1 = -1e30f;
#pragma unroll
        for (int nt = 0; nt < 8; nt++) {
            rm0 = fmaxf(rm0, fmaxf(sacc[nt][0], sacc[nt][1]));
            rm1 = fmaxf(rm1, fmaxf(sacc[nt][2], sacc[nt][3]));
        }
        rm0 = fmaxf(rm0, __shfl_xor_sync(0xffffffffu, rm0, 1));
        rm0 = fmaxf(rm0, __shfl_xor_sync(0xffffffffu, rm0, 2));
        rm1 = fmaxf(rm1, __shfl_xor_sync(0xffffffffu, rm1, 1));
        rm1 = fmaxf(rm1, __shfl_xor_sync(0xffffffffu, rm1, 2));

        float mn0 = fmaxf(m0, rm0), mn1 = fmaxf(m1, rm1);
        float corr0 = __expf(m0 - mn0), corr1 = __expf(m1 - mn1);
        float rs0 = 0.0f, rs1 = 0.0f;
#pragma unroll
        for (int nt = 0; nt < 8; nt++) {
            sacc[nt][0] = __expf(sacc[nt][0] - mn0);
            sacc[nt][1] = __expf(sacc[nt][1] - mn0);
            sacc[nt][2] = __expf(sacc[nt][2] - mn1);
            sacc[nt][3] = __expf(sacc[nt][3] - mn1);
            rs0 += sacc[nt][0] + sacc[nt][1];
            rs1 += sacc[nt][2] + sacc[nt][3];
        }
        rs0 += __shfl_xor_sync(0xffffffffu, rs0, 1);
        rs0 += __shfl_xor_sync(0xffffffffu, rs0, 2);
        rs1 += __shfl_xor_sync(0xffffffffu, rs1, 1);
        rs1 += __shfl_xor_sync(0xffffffffu, rs1, 2);

        l0 = l0 * corr0 + rs0;
        l1 = l1 * corr1 + rs1;
        m0 = mn0; m1 = mn1;
#pragma unroll
        for (int nt = 0; nt < 8; nt++) {
            oacc[nt][0] *= corr0; oacc[nt][1] *= corr0;
            oacc[nt][2] *= corr1; oacc[nt][3] *= corr1;
        }

        // ---- O += P V (3-term split; P from registers) ----
#pragma unroll
        for (int j = 0; j < 4; j++) {
            uint32_t ph[4], pl[4];
            split_pack(sacc[2 * j][0],     sacc[2 * j][1],     ph[0], pl[0]);
            split_pack(sacc[2 * j][2],     sacc[2 * j][3],     ph[1], pl[1]);
            split_pack(sacc[2 * j + 1][0], sacc[2 * j + 1][1], ph[2], pl[2]);
            split_pack(sacc[2 * j + 1][2], sacc[2 * j + 1][3], ph[3], pl[3]);
#pragma unroll
            for (int nd = 0; nd < 4; nd++) {
                uint32_t boff = sw128((uint32_t)((nd * 16 + b_row16) * 128 + j * 32 + b_koff));
                uint32_t vh[4], vl[4];
                ldsm4(vh, cb + FA_VHI + boff);
                ldsm4(vl, cb + FA_VLO + boff);
                mma16816(oacc[2 * nd],     ph, vh[0], vh[1]);
                mma16816(oacc[2 * nd],     ph, vl[0], vl[1]);
                mma16816(oacc[2 * nd],     pl, vh[0], vh[1]);
                mma16816(oacc[2 * nd + 1], ph, vh[2], vh[3]);
                mma16816(oacc[2 * nd + 1], ph, vl[2], vl[3]);
                mma16816(oacc[2 * nd + 1], pl, vh[2], vh[3]);
            }
        }
        __syncthreads();
    }

    // ---- epilogue: write split-bf16 O directly ----
    float inv0 = 1.0f / l0;
    float inv1 = 1.0f / l1;
    size_t orow0 = (size_t)(b * SEQ + bq * 128 + wid * 16 + grp) * DMODEL + h * 64;
#pragma unroll
    for (int nt = 0; nt < 8; nt++) {
        int col = nt * 8 + tig * 2;
        uint32_t h0, l0p, h1, l1p;
        split_pack(oacc[nt][0] * inv0, oacc[nt][1] * inv0, h0, l0p);
        split_pack(oacc[nt][2] * inv1, oacc[nt][3] * inv1, h1, l1p);
        *(uint32_t*)(Ohi + orow0 + col)                = h0;
        *(uint32_t*)(Olo + orow0 + col)                = l0p;
        *(uint32_t*)(Ohi + orow0 + 8 * DMODEL + col)   = h1;
        *(uint32_t*)(Olo + orow0 + 8 * DMODEL + col)   = l1p;
    }
}

// ---------------------------------------------------------------------------
// Launch
// ---------------------------------------------------------------------------
extern "C" void kernel_launch(void* const* d_in, const int* in_sizes, int n_in,
                              void* d_out, int out_size)
{
    const float* x  = (const float*)d_in[0];
    const float* Wq = (const float*)d_in[1];
    const float* Wk = (const float*)d_in[2];
    const float* Wv = (const float*)d_in[3];
    const float* Wo = (const float*)d_in[4];
    float* out = (float*)d_out;

    __nv_bfloat16 *xhi, *xlo, *ohi, *olo, *whi, *wlo;
    __nv_bfloat16 *Qh, *Ql, *Kh, *Kl, *Vth, *Vtl;
    cudaGetSymbolAddress((void**)&xhi, g_xhi);
    cudaGetSymbolAddress((void**)&xlo, g_xlo);
    cudaGetSymbolAddress((void**)&ohi, g_ohi);
    cudaGetSymbolAddress((void**)&olo, g_olo);
    cudaGetSymbolAddress((void**)&whi, g_whi);
    cudaGetSymbolAddress((void**)&wlo, g_wlo);
    cudaGetSymbolAddress((void**)&Qh,  g_Qhi);
    cudaGetSymbolAddress((void**)&Ql,  g_Qlo);
    cudaGetSymbolAddress((void**)&Kh,  g_Khi);
    cudaGetSymbolAddress((void**)&Kl,  g_Klo);
    cudaGetSymbolAddress((void**)&Vth, g_Vthi);
    cudaGetSymbolAddress((void**)&Vtl, g_Vtlo);

    const int WN  = DMODEL * DMODEL;
    const int xn4 = (MT * DMODEL) / 4;
    const int wn4 = WN / 4;

    dim3 xsGrid((xn4 + 255) / 256, 1, 1);
    split_bf16_kernel<<<xsGrid, 256>>>(
        (const float4*)x, nullptr, nullptr, nullptr,
        (__nv_bfloat162*)xhi, (__nv_bfloat162*)xlo, xn4);
    dim3 wsGrid((wn4 + 255) / 256, 1, 4);
    split_bf16_kernel<<<wsGrid, 256>>>(
        (const float4*)Wq, (const float4*)Wk, (const float4*)Wv, (const float4*)Wo,
        (__nv_bfloat162*)whi, (__nv_bfloat162*)wlo, wn4);

    cudaFuncSetAttribute(gemm_mma_kernel,
                         cudaFuncAttributeMaxDynamicSharedMemorySize, GSM_TOTAL);
    cudaFuncSetAttribute(fa_mma_kernel,
                         cudaFuncAttributeMaxDynamicSharedMemorySize, FA_TOTAL);

    // QKV projections: z=0 -> Q split, z=1 -> K split, z=2 -> V split transposed
    dim3 qkvGrid(DMODEL / 128, MT / 128, 3);
    gemm_mma_kernel<<<qkvGrid, 512, GSM_TOTAL>>>(
        xhi, xlo,
        whi + 0 * (size_t)WN, wlo + 0 * (size_t)WN,
        whi + 1 * (size_t)WN, wlo + 1 * (size_t)WN,
        whi + 2 * (size_t)WN, wlo + 2 * (size_t)WN,
        nullptr, Qh, Ql, Kh, Kl, Vth, Vtl, 1);

    // Flash attention (tensor-core, pipelined, writes split O)
    dim3 faGrid(SEQ / 128, BATCH * NHEADS);
    fa_mma_kernel<<<faGrid, 256, FA_TOTAL>>>(Qh, Ql, Kh, Kl, Vth, Vtl, ohi, olo);

    // O projection (reads split O directly)
    dim3 oGrid(DMODEL / 128, MT / 128, 1);
    gemm_mma_kernel<<<oGrid, 512, GSM_TOTAL>>>(
        ohi, olo,
        whi + 3 * (size_t)WN, wlo + 3 * (size_t)WN,
        whi + 3 * (size_t)WN, wlo + 3 * (size_t)WN,
        whi + 3 * (size_t)WN, wlo + 3 * (size_t)WN,
        out, nullptr, nullptr, nullptr, nullptr, nullptr, nullptr, 0);
}

// round 8
// speedup vs baseline: 3.5295x; 1.1771x over previous
#include <cuda_runtime.h>
#include <cuda_bf16.h>
#include <cuda_fp16.h>
#include <cstdint>

// Problem constants
#define BATCH   2
#define SEQ     2048
#define DMODEL  1024
#define NHEADS  16
#define DHEAD   64
#define MT      (BATCH * SEQ)        // 4096 rows

// ---------------------------------------------------------------------------
// Scratch (device globals: no cudaMalloc allowed)
// ---------------------------------------------------------------------------
__device__ __nv_bfloat16 g_xhi[MT * DMODEL];
__device__ __nv_bfloat16 g_xlo[MT * DMODEL];
__device__ __nv_bfloat16 g_ohi[MT * DMODEL];
__device__ __nv_bfloat16 g_olo[MT * DMODEL];
__device__ __nv_bfloat16 g_whi[4][DMODEL * DMODEL];
__device__ __nv_bfloat16 g_wlo[4][DMODEL * DMODEL];

__device__ __nv_bfloat16 g_Qhi[MT * DMODEL];   // pre-scaled by 1/8
__device__ __nv_bfloat16 g_Qlo[MT * DMODEL];
__device__ __nv_bfloat16 g_Khi[MT * DMODEL];
__device__ __nv_bfloat16 g_Klo[MT * DMODEL];
__device__ __half        g_Vt [MT * DMODEL];   // fp16, [b][h][d][t]

// ---------------------------------------------------------------------------
// Helpers (base ISA only — harness PTX target is compute_103, no tcgen05)
// ---------------------------------------------------------------------------
__device__ __forceinline__ uint32_t smem_u32(const void* p) {
    uint32_t a;
    asm("{ .reg .u64 t; cvta.to.shared.u64 t, %1; cvt.u32.u64 %0, t; }"
        : "=r"(a) : "l"(p));
    return a;
}

__device__ __forceinline__ uint32_t sw128(uint32_t off) {
    return off ^ ((off >> 3) & 0x70);
}

__device__ __forceinline__ void ldsm4(uint32_t* r, uint32_t addr) {
    asm volatile("ldmatrix.sync.aligned.m8n8.x4.shared.b16 {%0,%1,%2,%3}, [%4];"
        : "=r"(r[0]), "=r"(r[1]), "=r"(r[2]), "=r"(r[3]) : "r"(addr));
}

__device__ __forceinline__ void mma16816(float* c, const uint32_t* a,
                                         uint32_t b0, uint32_t b1) {
    asm volatile(
        "mma.sync.aligned.m16n8k16.row.col.f32.bf16.bf16.f32 "
        "{%0,%1,%2,%3}, {%4,%5,%6,%7}, {%8,%9}, {%0,%1,%2,%3};"
        : "+f"(c[0]), "+f"(c[1]), "+f"(c[2]), "+f"(c[3])
        : "r"(a[0]), "r"(a[1]), "r"(a[2]), "r"(a[3]), "r"(b0), "r"(b1));
}

__device__ __forceinline__ void mma16816h(float* c, const uint32_t* a,
                                          uint32_t b0, uint32_t b1) {
    asm volatile(
        "mma.sync.aligned.m16n8k16.row.col.f32.f16.f16.f32 "
        "{%0,%1,%2,%3}, {%4,%5,%6,%7}, {%8,%9}, {%0,%1,%2,%3};"
        : "+f"(c[0]), "+f"(c[1]), "+f"(c[2]), "+f"(c[3])
        : "r"(a[0]), "r"(a[1]), "r"(a[2]), "r"(a[3]), "r"(b0), "r"(b1));
}

__device__ __forceinline__ void cp16(uint32_t dst, const void* src) {
    asm volatile("cp.async.cg.shared.global [%0], [%1], 16;"
                 :: "r"(dst), "l"(src));
}
#define CP_COMMIT()  asm volatile("cp.async.commit_group;")
#define CP_WAIT(N)   asm volatile("cp.async.wait_group %0;" :: "n"(N))

// split two floats into packed bf16 hi/lo pairs
__device__ __forceinline__ void split_pack(float x, float y, uint32_t& hi, uint32_t& lo) {
    __nv_bfloat16 hx = __float2bfloat16(x), hy = __float2bfloat16(y);
    __nv_bfloat16 lx = __float2bfloat16(x - __bfloat162float(hx));
    __nv_bfloat16 ly = __float2bfloat16(y - __bfloat162float(hy));
    __nv_bfloat162 h2 = __halves2bfloat162(hx, hy);
    __nv_bfloat162 l2 = __halves2bfloat162(lx, ly);
    hi = *(uint32_t*)&h2;
    lo = *(uint32_t*)&l2;
}

__device__ __forceinline__ uint32_t pack_h2(float x, float y) {
    __half2 h = __floats2half2_rn(x, y);
    return *(uint32_t*)&h;
}

// ---------------------------------------------------------------------------
// fp32 -> (bf16 hi, bf16 lo) split conversion. grid.z picks one of the inputs.
// ---------------------------------------------------------------------------
__global__ void __launch_bounds__(256) split_bf16_kernel(
    const float4* __restrict__ in0, const float4* __restrict__ in1,
    const float4* __restrict__ in2, const float4* __restrict__ in3,
    __nv_bfloat162* __restrict__ hi,
    __nv_bfloat162* __restrict__ lo,
    int n4)
{
    int i = blockIdx.x * blockDim.x + threadIdx.x;
    if (i >= n4) return;
    int z = blockIdx.z;
    const float4* in = (z == 0) ? in0 : (z == 1) ? in1 : (z == 2) ? in2 : in3;
    size_t o = (size_t)z * n4 + i;
    float4 v = in[i];
    uint32_t h0, l0, h1, l1;
    split_pack(v.x, v.y, h0, l0);
    split_pack(v.z, v.w, h1, l1);
    ((uint32_t*)hi)[2 * o]     = h0;
    ((uint32_t*)hi)[2 * o + 1] = h1;
    ((uint32_t*)lo)[2 * o]     = l0;
    ((uint32_t*)lo)[2 * o + 1] = l1;
}

// ---------------------------------------------------------------------------
// Split-bf16 GEMM via mma.sync, cp.async 2-stage pipelined.
// C[M,N] = A[M,K] * B[N,K]^T ;  C = Ahi*Bhi + Ahi*Blo + Alo*Bhi
// CTA: 128x128 tile, 512 threads = 16 warps (4 M x 4 N), warp tile 32x32.
// qkv=1: z=0 -> Q split-bf16 scaled by 1/8; z=1 -> K split-bf16;
//        z=2 -> V fp16, transposed per head ([b][h][d][t]).
// qkv=0: fp32 out to C.
// ---------------------------------------------------------------------------
#define TILE_BYTES 16384                  // 128*64*2
#define SA_HI 0
#define SA_LO (SA_HI + TILE_BYTES)
#define SB_HI (SA_LO + TILE_BYTES)
#define SB_LO (SB_HI + TILE_BYTES)
#define GSTAGE (4 * TILE_BYTES)           // 64 KB per stage
#define GSM_TOTAL (2 * GSTAGE)            // 128 KB

__global__ void __launch_bounds__(512) gemm_mma_kernel(
    const __nv_bfloat16* __restrict__ Ahi, const __nv_bfloat16* __restrict__ Alo,
    const __nv_bfloat16* __restrict__ B0h, const __nv_bfloat16* __restrict__ B0l,
    const __nv_bfloat16* __restrict__ B1h, const __nv_bfloat16* __restrict__ B1l,
    const __nv_bfloat16* __restrict__ B2h, const __nv_bfloat16* __restrict__ B2l,
    float* __restrict__ C,
    __nv_bfloat16* __restrict__ Qh, __nv_bfloat16* __restrict__ Ql,
    __nv_bfloat16* __restrict__ Kh, __nv_bfloat16* __restrict__ Kl,
    __half* __restrict__ Vt,
    int qkv)
{
    extern __shared__ char smem[];
    const uint32_t sbase = smem_u32(smem);

    const int tid  = threadIdx.x;
    const int wid  = tid >> 5;            // 0..15
    const int lane = tid & 31;
    const int warp_m = wid & 3;
    const int warp_n = wid >> 2;
    const int bn = blockIdx.x;
    const int bm = blockIdx.y;
    const int z  = blockIdx.z;

    const __nv_bfloat16* Bh = (z == 0) ? B0h : (z == 1) ? B1h : B2h;
    const __nv_bfloat16* Bl = (z == 0) ? B0l : (z == 1) ? B1l : B2l;

    float acc[2][4][4];
#pragma unroll
    for (int i = 0; i < 2; i++)
#pragma unroll
        for (int j = 0; j < 4; j++)
#pragma unroll
            for (int k = 0; k < 4; k++) acc[i][j][k] = 0.0f;

    const int trow = tid >> 2;
    const int tcol = (tid & 3) * 32;

    const char* gAh = (const char*)(Ahi + (size_t)(bm * 128 + trow) * DMODEL) + tcol;
    const char* gAl = (const char*)(Alo + (size_t)(bm * 128 + trow) * DMODEL) + tcol;
    const char* gBh = (const char*)(Bh  + (size_t)(bn * 128 + trow) * DMODEL) + tcol;
    const char* gBl = (const char*)(Bl  + (size_t)(bn * 128 + trow) * DMODEL) + tcol;

    uint32_t stofs[2];
#pragma unroll
    for (int i = 0; i < 2; i++)
        stofs[i] = sw128((uint32_t)(trow * 128 + tcol + i * 16));

    const int a_row16 = lane & 15;
    const int a_koff  = (lane >> 4) * 16;
    const int b_row16 = (lane & 7) | ((lane & 16) >> 1);
    const int b_koff  = ((lane >> 3) & 1) * 16;

#pragma unroll
    for (int i = 0; i < 2; i++) {
        cp16(sbase + SA_HI + stofs[i], gAh + i * 16);
        cp16(sbase + SA_LO + stofs[i], gAl + i * 16);
        cp16(sbase + SB_HI + stofs[i], gBh + i * 16);
        cp16(sbase + SB_LO + stofs[i], gBl + i * 16);
    }
    CP_COMMIT();

    for (int t = 0; t < DMODEL / 64; t++) {
        if (t < DMODEL / 64 - 1) {
            const int gofs = (t + 1) * 128;
            const uint32_t sb = sbase + ((t + 1) & 1) * GSTAGE;
#pragma unroll
            for (int i = 0; i < 2; i++) {
                cp16(sb + SA_HI + stofs[i], gAh + gofs + i * 16);
                cp16(sb + SA_LO + stofs[i], gAl + gofs + i * 16);
                cp16(sb + SB_HI + stofs[i], gBh + gofs + i * 16);
                cp16(sb + SB_LO + stofs[i], gBl + gofs + i * 16);
            }
            CP_COMMIT();
            CP_WAIT(1);
        } else {
            CP_WAIT(0);
        }
        __syncthreads();

        const uint32_t cb = sbase + (t & 1) * GSTAGE;
#pragma unroll
        for (int k16 = 0; k16 < 4; k16++) {
            const int kb = k16 * 32;
            uint32_t ah[2][4], al[2][4];
#pragma unroll
            for (int mt = 0; mt < 2; mt++) {
                int r = warp_m * 32 + mt * 16 + a_row16;
                uint32_t off = sw128((uint32_t)(r * 128 + kb + a_koff));
                ldsm4(ah[mt], cb + SA_HI + off);
                ldsm4(al[mt], cb + SA_LO + off);
            }
#pragma unroll
            for (int np = 0; np < 2; np++) {
                int nr = warp_n * 32 + np * 16 + b_row16;
                uint32_t off = sw128((uint32_t)(nr * 128 + kb + b_koff));
                uint32_t bhf[4], blf[4];
                ldsm4(bhf, cb + SB_HI + off);
                ldsm4(blf, cb + SB_LO + off);
#pragma unroll
                for (int mt = 0; mt < 2; mt++) {
                    mma16816(acc[mt][2 * np],     ah[mt], bhf[0], bhf[1]);
                    mma16816(acc[mt][2 * np],     ah[mt], blf[0], blf[1]);
                    mma16816(acc[mt][2 * np],     al[mt], bhf[0], bhf[1]);
                    mma16816(acc[mt][2 * np + 1], ah[mt], bhf[2], bhf[3]);
                    mma16816(acc[mt][2 * np + 1], ah[mt], blf[2], blf[3]);
                    mma16816(acc[mt][2 * np + 1], al[mt], bhf[2], bhf[3]);
                }
            }
        }
        __syncthreads();
    }

    // ---- epilogue ----
    const int mode = qkv ? ((z == 2) ? 2 : 1) : 0;
    const int grp = lane >> 2;
    const int tig = lane & 3;
    __nv_bfloat16* Hp = (z == 0) ? Qh : Kh;
    __nv_bfloat16* Lp = (z == 0) ? Ql : Kl;
    const float qscale = (z == 0) ? 0.125f : 1.0f;   // fold softmax scale into Q

#pragma unroll
    for (int mt = 0; mt < 2; mt++) {
        int row = bm * 128 + warp_m * 32 + mt * 16 + grp;
#pragma unroll
        for (int nt = 0; nt < 4; nt++) {
            int col = bn * 128 + warp_n * 32 + nt * 8 + tig * 2;
            float v00 = acc[mt][nt][0], v01 = acc[mt][nt][1];
            float v10 = acc[mt][nt][2], v11 = acc[mt][nt][3];
            if (mode == 0) {
                *(float2*)(C + (size_t)row * DMODEL + col)       = make_float2(v00, v01);
                *(float2*)(C + (size_t)(row + 8) * DMODEL + col) = make_float2(v10, v11);
            } else if (mode == 1) {
                uint32_t h0, l0, h1, l1;
                split_pack(v00 * qscale, v01 * qscale, h0, l0);
                split_pack(v10 * qscale, v11 * qscale, h1, l1);
                *(uint32_t*)(Hp + (size_t)row * DMODEL + col)       = h0;
                *(uint32_t*)(Hp + (size_t)(row + 8) * DMODEL + col) = h1;
                *(uint32_t*)(Lp + (size_t)row * DMODEL + col)       = l0;
                *(uint32_t*)(Lp + (size_t)(row + 8) * DMODEL + col) = l1;
            } else {
                int bb = row >> 11;
                int tt = row & (SEQ - 1);
                size_t base0 = (size_t)(bb * DMODEL + col) * SEQ;
                size_t base1 = (size_t)(bb * DMODEL + col + 1) * SEQ;
                Vt[base0 + tt]     = __float2half(v00);
                Vt[base1 + tt]     = __float2half(v01);
                Vt[base0 + tt + 8] = __float2half(v10);
                Vt[base1 + tt + 8] = __float2half(v11);
            }
        }
    }
}

// ---------------------------------------------------------------------------
// Flash attention via mma.sync, cp.async 2-stage pipelined K/V.
// CTA: 64 q-rows x d=64, kv tiles of 64. 128 threads = 4 warps.
// S = QK^T: bf16 3-term split (Q pre-scaled by 1/8).
// O += P V:  single fp16 MMA (P, V fp16).
// smem: 2 stages x (Khi,Klo,Vf16)[64][64] = 2 x 24 KB, + Q hi/lo 16 KB = 64 KB.
// Writes split-bf16 O directly.
// ---------------------------------------------------------------------------
#define FA_TILE 8192
#define FA_KHI 0
#define FA_KLO (FA_KHI + FA_TILE)
#define FA_VH  (FA_KLO + FA_TILE)
#define FA_STAGE (3 * FA_TILE)            // 24 KB
#define FA_QHI (2 * FA_STAGE)             // 49152
#define FA_QLO (FA_QHI + FA_TILE)
#define FA_TOTAL (FA_QLO + FA_TILE)       // 65536

__global__ void __launch_bounds__(128) fa_mma_kernel(
    const __nv_bfloat16* __restrict__ Qhi, const __nv_bfloat16* __restrict__ Qlo,
    const __nv_bfloat16* __restrict__ Khi, const __nv_bfloat16* __restrict__ Klo,
    const __half* __restrict__ Vt,
    __nv_bfloat16* __restrict__ Ohi, __nv_bfloat16* __restrict__ Olo)
{
    extern __shared__ char smem[];
    const uint32_t sbase = smem_u32(smem);
    const int tid  = threadIdx.x;
    const int wid  = tid >> 5;
    const int lane = tid & 31;
    const int bq = (int)gridDim.x - 1 - (int)blockIdx.x;   // longest first
    const int bh = blockIdx.y;
    const int b  = bh >> 4;
    const int h  = bh & 15;

    const int grp = lane >> 2;
    const int tig = lane & 3;
    const int a_row16 = lane & 15;
    const int a_koff  = (lane >> 4) * 16;
    const int b_row16 = (lane & 7) | ((lane & 16) >> 1);
    const int b_koff  = ((lane >> 3) & 1) * 16;

    const char* gkh = (const char*)Khi + ((size_t)(b * SEQ) * DMODEL + h * 64) * 2;
    const char* gkl = (const char*)Klo + ((size_t)(b * SEQ) * DMODEL + h * 64) * 2;
    const char* gvh = (const char*)Vt  + ((size_t)bh * DHEAD * SEQ) * 2;

    // staging: 4 iters, each (row = f>>3 in 0..63, 16B col)
    int srow[4], sc16[4];
    uint32_t sofs[4];
#pragma unroll
    for (int u = 0; u < 4; u++) {
        int f = u * 128 + tid;
        srow[u] = f >> 3;
        sc16[u] = (f & 7) * 16;
        sofs[u] = sw128((uint32_t)(srow[u] * 128 + sc16[u]));
    }

    // ---- stage Q (hi+lo) + K/V tile 0 ----
    {
        const char* gqh = (const char*)Qhi + ((size_t)(b * SEQ + bq * 64) * DMODEL + h * 64) * 2;
        const char* gql = (const char*)Qlo + ((size_t)(b * SEQ + bq * 64) * DMODEL + h * 64) * 2;
#pragma unroll
        for (int u = 0; u < 4; u++) {
            cp16(sbase + FA_QHI + sofs[u], gqh + (size_t)srow[u] * DMODEL * 2 + sc16[u]);
            cp16(sbase + FA_QLO + sofs[u], gql + (size_t)srow[u] * DMODEL * 2 + sc16[u]);
            size_t ko = ((size_t)srow[u] * DMODEL) * 2 + sc16[u];
            cp16(sbase + FA_KHI + sofs[u], gkh + ko);
            cp16(sbase + FA_KLO + sofs[u], gkl + ko);
            size_t vo = ((size_t)srow[u] * SEQ) * 2 + sc16[u];
            cp16(sbase + FA_VH + sofs[u], gvh + vo);
        }
        CP_COMMIT();
    }

    float oacc[8][4];
#pragma unroll
    for (int i = 0; i < 8; i++)
#pragma unroll
        for (int j = 0; j < 4; j++) oacc[i][j] = 0.0f;
    float m0 = -1e30f, m1 = -1e30f, l0 = 0.0f, l1 = 0.0f;

    const int qrow0 = wid * 16 + grp;

    for (int kb = 0; kb <= bq; kb++) {
        if (kb < bq) {
            const uint32_t sb = sbase + ((kb + 1) & 1) * FA_STAGE;
#pragma unroll
            for (int u = 0; u < 4; u++) {
                size_t ko = ((size_t)((kb + 1) * 64 + srow[u]) * DMODEL) * 2 + sc16[u];
                cp16(sb + FA_KHI + sofs[u], gkh + ko);
                cp16(sb + FA_KLO + sofs[u], gkl + ko);
                size_t vo = ((size_t)srow[u] * SEQ + (kb + 1) * 64) * 2 + sc16[u];
                cp16(sb + FA_VH + sofs[u], gvh + vo);
            }
            CP_COMMIT();
            CP_WAIT(1);
        } else {
            CP_WAIT(0);
        }
        __syncthreads();

        const uint32_t cb = sbase + (kb & 1) * FA_STAGE;

        // ---- S = Q K^T (3-term bf16 split; scale pre-folded into Q) ----
        float sacc[8][4];
#pragma unroll
        for (int i = 0; i < 8; i++)
#pragma unroll
            for (int j = 0; j < 4; j++) sacc[i][j] = 0.0f;

#pragma unroll
        for (int k16 = 0; k16 < 4; k16++) {
            uint32_t ah[4], al[4];
            uint32_t aoff = sw128((uint32_t)((wid * 16 + a_row16) * 128 + k16 * 32 + a_koff));
            ldsm4(ah, sbase + FA_QHI + aoff);
            ldsm4(al, sbase + FA_QLO + aoff);
#pragma unroll
            for (int np = 0; np < 4; np++) {
                uint32_t boff = sw128((uint32_t)((np * 16 + b_row16) * 128 + k16 * 32 + b_koff));
                uint32_t bhf[4], blf[4];
                ldsm4(bhf, cb + FA_KHI + boff);
                ldsm4(blf, cb + FA_KLO + boff);
                mma16816(sacc[2 * np],     ah, bhf[0], bhf[1]);
                mma16816(sacc[2 * np],     ah, blf[0], blf[1]);
                mma16816(sacc[2 * np],     al, bhf[0], bhf[1]);
                mma16816(sacc[2 * np + 1], ah, bhf[2], bhf[3]);
                mma16816(sacc[2 * np + 1], ah, blf[2], blf[3]);
                mma16816(sacc[2 * np + 1], al, bhf[2], bhf[3]);
            }
        }

        // ---- causal mask (diagonal tile only) ----
        if (kb == bq) {
#pragma unroll
            for (int nt = 0; nt < 8; nt++) {
                int c = nt * 8 + tig * 2;
                if (c     > qrow0)     sacc[nt][0] = -1e30f;
                if (c + 1 > qrow0)     sacc[nt][1] = -1e30f;
                if (c     > qrow0 + 8) sacc[nt][2] = -1e30f;
                if (c + 1 > qrow0 + 8) sacc[nt][3] = -1e30f;
            }
        }

        // ---- online softmax ----
        float rm0 = -1e30f, rm1 = -1e30f;
#pragma unroll
        for (int nt = 0; nt < 8; nt++) {
            rm0 = fmaxf(rm0, fmaxf(sacc[nt][0], sacc[nt][1]));
            rm1 = fmaxf(rm1, fmaxf(sacc[nt][2], sacc[nt][3]));
        }
        rm0 = fmaxf(rm0, __shfl_xor_sync(0xffffffffu, rm0, 1));
        rm0 = fmaxf(rm0, __shfl_xor_sync(0xffffffffu, rm0, 2));
        rm1 = fmaxf(rm1, __shfl_xor_sync(0xffffffffu, rm1, 1));
        rm1 = fmaxf(rm1, __shfl_xor_sync(0xffffffffu, rm1, 2));

        float mn0 = fmaxf(m0, rm0), mn1 = fmaxf(m1, rm1);
        float corr0 = __expf(m0 - mn0), corr1 = __expf(m1 - mn1);
        float rs0 = 0.0f, rs1 = 0.0f;
#pragma unroll
        for (int nt = 0; nt < 8; nt++) {
            sacc[nt][0] = __expf(sacc[nt][0] - mn0);
            sacc[nt][1] = __expf(sacc[nt][1] - mn0);
            sacc[nt][2] = __expf(sacc[nt][2] - mn1);
            sacc[nt][3] = __expf(sacc[nt][3] - mn1);
            rs0 += sacc[nt][0] + sacc[nt][1];
            rs1 += sacc[nt][2] + sacc[nt][3];
        }
        rs0 += __shfl_xor_sync(0xffffffffu, rs0, 1);
        rs0 += __shfl_xor_sync(0xffffffffu, rs0, 2);
        rs1 += __shfl_xor_sync(0xffffffffu, rs1, 1);
        rs1 += __shfl_xor_sync(0xffffffffu, rs1, 2);

        l0 = l0 * corr0 + rs0;
        l1 = l1 * corr1 + rs1;
        m0 = mn0; m1 = mn1;
#pragma unroll
        for (int nt = 0; nt < 8; nt++) {
            oacc[nt][0] *= corr0; oacc[nt][1] *= corr0;
            oacc[nt][2] *= corr1; oacc[nt][3] *= corr1;
        }

        // ---- O += P V  (single fp16 MMA; P packed from registers) ----
#pragma unroll
        for (int j = 0; j < 4; j++) {
            uint32_t pf[4];
            pf[0] = pack_h2(sacc[2 * j][0],     sacc[2 * j][1]);
            pf[1] = pack_h2(sacc[2 * j][2],     sacc[2 * j][3]);
            pf[2] = pack_h2(sacc[2 * j + 1][0], sacc[2 * j + 1][1]);
            pf[3] = pack_h2(sacc[2 * j + 1][2], sacc[2 * j + 1][3]);
#pragma unroll
            for (int nd = 0; nd < 4; nd++) {
                uint32_t boff = sw128((uint32_t)((nd * 16 + b_row16) * 128 + j * 32 + b_koff));
                uint32_t vh[4];
                ldsm4(vh, cb + FA_VH + boff);
                mma16816h(oacc[2 * nd],     pf, vh[0], vh[1]);
                mma16816h(oacc[2 * nd + 1], pf, vh[2], vh[3]);
            }
        }
        __syncthreads();
    }

    // ---- epilogue: write split-bf16 O directly ----
    float inv0 = 1.0f / l0;
    float inv1 = 1.0f / l1;
    size_t orow0 = (size_t)(b * SEQ + bq * 64 + wid * 16 + grp) * DMODEL + h * 64;
#pragma unroll
    for (int nt = 0; nt < 8; nt++) {
        int col = nt * 8 + tig * 2;
        uint32_t h0, l0p, h1, l1p;
        split_pack(oacc[nt][0] * inv0, oacc[nt][1] * inv0, h0, l0p);
        split_pack(oacc[nt][2] * inv1, oacc[nt][3] * inv1, h1, l1p);
        *(uint32_t*)(Ohi + orow0 + col)                = h0;
        *(uint32_t*)(Olo + orow0 + col)                = l0p;
        *(uint32_t*)(Ohi + orow0 + 8 * DMODEL + col)   = h1;
        *(uint32_t*)(Olo + orow0 + 8 * DMODEL + col)   = l1p;
    }
}

// ---------------------------------------------------------------------------
// Launch
// ---------------------------------------------------------------------------
extern "C" void kernel_launch(void* const* d_in, const int* in_sizes, int n_in,
                              void* d_out, int out_size)
{
    const float* x  = (const float*)d_in[0];
    const float* Wq = (const float*)d_in[1];
    const float* Wk = (const float*)d_in[2];
    const float* Wv = (const float*)d_in[3];
    const float* Wo = (const float*)d_in[4];
    float* out = (float*)d_out;

    __nv_bfloat16 *xhi, *xlo, *ohi, *olo, *whi, *wlo;
    __nv_bfloat16 *Qh, *Ql, *Kh, *Kl;
    __half *Vt;
    cudaGetSymbolAddress((void**)&xhi, g_xhi);
    cudaGetSymbolAddress((void**)&xlo, g_xlo);
    cudaGetSymbolAddress((void**)&ohi, g_ohi);
    cudaGetSymbolAddress((void**)&olo, g_olo);
    cudaGetSymbolAddress((void**)&whi, g_whi);
    cudaGetSymbolAddress((void**)&wlo, g_wlo);
    cudaGetSymbolAddress((void**)&Qh,  g_Qhi);
    cudaGetSymbolAddress((void**)&Ql,  g_Qlo);
    cudaGetSymbolAddress((void**)&Kh,  g_Khi);
    cudaGetSymbolAddress((void**)&Kl,  g_Klo);
    cudaGetSymbolAddress((void**)&Vt,  g_Vt);

    const int WN  = DMODEL * DMODEL;
    const int xn4 = (MT * DMODEL) / 4;
    const int wn4 = WN / 4;

    dim3 xsGrid((xn4 + 255) / 256, 1, 1);
    split_bf16_kernel<<<xsGrid, 256>>>(
        (const float4*)x, nullptr, nullptr, nullptr,
        (__nv_bfloat162*)xhi, (__nv_bfloat162*)xlo, xn4);
    dim3 wsGrid((wn4 + 255) / 256, 1, 4);
    split_bf16_kernel<<<wsGrid, 256>>>(
        (const float4*)Wq, (const float4*)Wk, (const float4*)Wv, (const float4*)Wo,
        (__nv_bfloat162*)whi, (__nv_bfloat162*)wlo, wn4);

    cudaFuncSetAttribute(gemm_mma_kernel,
                         cudaFuncAttributeMaxDynamicSharedMemorySize, GSM_TOTAL);
    cudaFuncSetAttribute(fa_mma_kernel,
                         cudaFuncAttributeMaxDynamicSharedMemorySize, FA_TOTAL);

    // QKV projections: z=0 -> Q split (scaled), z=1 -> K split, z=2 -> V fp16 T
    dim3 qkvGrid(DMODEL / 128, MT / 128, 3);
    gemm_mma_kernel<<<qkvGrid, 512, GSM_TOTAL>>>(
        xhi, xlo,
        whi + 0 * (size_t)WN, wlo + 0 * (size_t)WN,
        whi + 1 * (size_t)WN, wlo + 1 * (size_t)WN,
        whi + 2 * (size_t)WN, wlo + 2 * (size_t)WN,
        nullptr, Qh, Ql, Kh, Kl, Vt, 1);

    // Flash attention (tensor-core, pipelined, writes split O)
    dim3 faGrid(SEQ / 64, BATCH * NHEADS);
    fa_mma_kernel<<<faGrid, 128, FA_TOTAL>>>(Qh, Ql, Kh, Kl, Vt, ohi, olo);

    // O projection (reads split O directly)
    dim3 oGrid(DMODEL / 128, MT / 128, 1);
    gemm_mma_kernel<<<oGrid, 512, GSM_TOTAL>>>(
        ohi, olo,
        whi + 3 * (size_t)WN, wlo + 3 * (size_t)WN,
        whi + 3 * (size_t)WN, wlo + 3 * (size_t)WN,
        whi + 3 * (size_t)WN, wlo + 3 * (size_t)WN,
        out, nullptr, nullptr, nullptr, nullptr, nullptr, 0);
}